// round 2
// baseline (speedup 1.0000x reference)
#include <cuda_runtime.h>
#include <math.h>

// ----------------------------------------------------------------------------
// NoiseRobustAttractorLayer  (B=16,S=4096,IN=512,HID=512,NH=4,HD=128,NA=8)
// T = 65536 tokens. All fp32.
// Pipeline:
//   K1: LN(x) -> xn ; gate = sigmoid(xn . gW[h] + gb[h])
//   K2: h = gelu(LN(xn @ hW1[h] + hb1[h]))          [per head, N=256]
//   K3: state = h @ hW2[h] + hb2 ; dyn = state@dynamics[h];
//       attractor softmax; head_out -> comb [T,512]
//   K4: o1 = gelu(LN(comb @ oW1 + ob1))
//   K5: out = xn + o1 @ oW2 + ob2
// ----------------------------------------------------------------------------

#define T_TOK 65536
#define EPSV  1e-5f

// scratch (static device allocations — no cudaMalloc allowed)
__device__ float g_xn  [(size_t)T_TOK * 512];   // 134 MB
__device__ float g_gate[(size_t)T_TOK * 4];     //   1 MB
__device__ float g_h   [(size_t)T_TOK * 1024];  // 268 MB
__device__ float g_comb[(size_t)T_TOK * 512];   // 134 MB
__device__ float g_oact[(size_t)T_TOK * 512];   // 134 MB

__device__ __forceinline__ float warp_sum(float v) {
#pragma unroll
    for (int o = 16; o > 0; o >>= 1) v += __shfl_xor_sync(0xffffffffu, v, o);
    return v;
}

// block reduction for 128 threads (4 warps)
__device__ __forceinline__ float block_sum_128(float v, float* s) {
    v = warp_sum(v);
    int w = threadIdx.x >> 5;
    __syncthreads();
    if ((threadIdx.x & 31) == 0) s[w] = v;
    __syncthreads();
    return s[0] + s[1] + s[2] + s[3];
}

__device__ __forceinline__ float gelu_exact(float x) {
    return 0.5f * x * (1.0f + erff(x * 0.70710678118654752f));
}

// ============================================================================
// K1: layernorm of x + gate logits.  blockDim = 128, grid-stride over tokens.
// ============================================================================
__global__ void __launch_bounds__(128) k_ln_gate(
    const float* __restrict__ x, const float* __restrict__ ng,
    const float* __restrict__ nb, const float* __restrict__ gW,
    const float* __restrict__ gb)
{
    __shared__ float sred[4];
    __shared__ float sgW[2048];
    __shared__ float sng[512], snb[512];
    int tid = threadIdx.x;
    for (int i = tid; i < 2048; i += 128) sgW[i] = gW[i];
    for (int i = tid; i < 512; i += 128) { sng[i] = ng[i]; snb[i] = nb[i]; }
    __syncthreads();

    for (int t = blockIdx.x; t < T_TOK; t += gridDim.x) {
        const float* xr = x + (size_t)t * 512;
        float v[4];
#pragma unroll
        for (int j = 0; j < 4; j++) v[j] = xr[tid + 128 * j];
        float s = block_sum_128(v[0] + v[1] + v[2] + v[3], sred);
        float m = s * (1.0f / 512.0f);
        float q = 0.f;
#pragma unroll
        for (int j = 0; j < 4; j++) { float d = v[j] - m; q += d * d; }
        q = block_sum_128(q, sred);
        float rs = rsqrtf(q * (1.0f / 512.0f) + EPSV);
        float xn[4];
#pragma unroll
        for (int j = 0; j < 4; j++) {
            int i = tid + 128 * j;
            xn[j] = (v[j] - m) * rs * sng[i] + snb[i];
            g_xn[(size_t)t * 512 + i] = xn[j];
        }
#pragma unroll
        for (int h = 0; h < 4; h++) {
            float p = 0.f;
#pragma unroll
            for (int j = 0; j < 4; j++) p += xn[j] * sgW[h * 512 + tid + 128 * j];
            p = block_sum_128(p, sred);
            if (tid == 0) g_gate[(size_t)t * 4 + h] = 1.0f / (1.0f + expf(-(p + gb[h])));
        }
    }
}

// ============================================================================
// K2: per-head MLP layer 1 + per-head LN + GELU.
// grid (T/64, NH), blockDim 256.  Tile M=64 tokens x N=256 cols, K=512.
// warp w owns rows w*8..w*8+7 ; lane l owns cols l+32c (c=0..7)
// ============================================================================
__global__ void __launch_bounds__(256) k_head1(
    const float* __restrict__ hW1, const float* __restrict__ hb1,
    const float* __restrict__ hlg, const float* __restrict__ hlb)
{
    int h = blockIdx.y;
    int t0 = blockIdx.x * 64;
    __shared__ float As[16][65];
    __shared__ float Bs[16][256];
    int tid = threadIdx.x, w = tid >> 5, l = tid & 31;
    float acc[8][8];
#pragma unroll
    for (int r = 0; r < 8; r++)
#pragma unroll
        for (int c = 0; c < 8; c++) acc[r][c] = 0.f;

    const float* Wh = hW1 + (size_t)h * 512 * 256;
    int arow = tid >> 2, ac = (tid & 3) * 4;

    for (int k0 = 0; k0 < 512; k0 += 16) {
        float4 a = *(const float4*)(g_xn + (size_t)(t0 + arow) * 512 + k0 + ac);
        As[ac + 0][arow] = a.x; As[ac + 1][arow] = a.y;
        As[ac + 2][arow] = a.z; As[ac + 3][arow] = a.w;
#pragma unroll
        for (int j = 0; j < 4; j++) {
            int idx = tid + 256 * j;
            int kk = idx >> 6, col = (idx & 63) * 4;
            *(float4*)&Bs[kk][col] = *(const float4*)(Wh + (size_t)(k0 + kk) * 256 + col);
        }
        __syncthreads();
#pragma unroll
        for (int kk = 0; kk < 16; kk++) {
            float av[8], bv[8];
#pragma unroll
            for (int r = 0; r < 8; r++) av[r] = As[kk][w * 8 + r];
#pragma unroll
            for (int c = 0; c < 8; c++) bv[c] = Bs[kk][l + 32 * c];
#pragma unroll
            for (int r = 0; r < 8; r++)
#pragma unroll
                for (int c = 0; c < 8; c++) acc[r][c] += av[r] * bv[c];
        }
        __syncthreads();
    }

    float bb[8], lg[8], lb[8];
#pragma unroll
    for (int c = 0; c < 8; c++) {
        int col = l + 32 * c;
        bb[c] = hb1[h * 256 + col];
        lg[c] = hlg[h * 256 + col];
        lb[c] = hlb[h * 256 + col];
    }
#pragma unroll
    for (int r = 0; r < 8; r++) {
        int row = w * 8 + r;
        float vv[8];
        float s = 0.f, s2 = 0.f;
#pragma unroll
        for (int c = 0; c < 8; c++) {
            vv[c] = acc[r][c] + bb[c];
            s += vv[c]; s2 += vv[c] * vv[c];
        }
        s = warp_sum(s); s2 = warp_sum(s2);
        float m = s * (1.0f / 256.0f);
        float var = s2 * (1.0f / 256.0f) - m * m;
        float rs = rsqrtf(var + EPSV);
        float* op = g_h + (size_t)(t0 + row) * 1024 + h * 256;
#pragma unroll
        for (int c = 0; c < 8; c++) {
            float u = (vv[c] - m) * rs * lg[c] + lb[c];
            op[l + 32 * c] = gelu_exact(u);
        }
    }
}

// ============================================================================
// K3: state = h@hW2 + hb2 ; dyn = state@dynamics ; attractor softmax mix.
// grid (T/64, NH), blockDim 256. M=64, N=128.
// warp w owns rows w*8..w*8+7; lane l owns cols l+32c (c=0..3)
// ============================================================================
__global__ void __launch_bounds__(256) k_head2(
    const float* __restrict__ hW2, const float* __restrict__ hb2,
    const float* __restrict__ attr, const float* __restrict__ dynm)
{
    int h = blockIdx.y;
    int t0 = blockIdx.x * 64;
    __shared__ float As[16][65];
    __shared__ float Bs[16][128];
    __shared__ float Ss[64][132];
    __shared__ float At[8][128];
    __shared__ float a2s[8];
    int tid = threadIdx.x, w = tid >> 5, l = tid & 31;

    // attractors -> smem (8x128 = 1024 floats, one float4 per thread)
    *(float4*)&At[tid >> 5][(tid & 31) * 4] =
        *(const float4*)(attr + (size_t)h * 1024 + tid * 4);
    __syncthreads();
    if (tid < 8) {
        float q = 0.f;
#pragma unroll
        for (int k = 0; k < 128; k++) q += At[tid][k] * At[tid][k];
        a2s[tid] = q;
    }

    float acc[8][4];
#pragma unroll
    for (int r = 0; r < 8; r++)
#pragma unroll
        for (int c = 0; c < 4; c++) acc[r][c] = 0.f;

    const float* W2 = hW2 + (size_t)h * 256 * 128;
    int arow = tid >> 2, ac = (tid & 3) * 4;

    for (int k0 = 0; k0 < 256; k0 += 16) {
        float4 a = *(const float4*)(g_h + (size_t)(t0 + arow) * 1024 + h * 256 + k0 + ac);
        As[ac + 0][arow] = a.x; As[ac + 1][arow] = a.y;
        As[ac + 2][arow] = a.z; As[ac + 3][arow] = a.w;
#pragma unroll
        for (int j = 0; j < 2; j++) {
            int idx = tid + 256 * j;
            int kk = idx >> 5, col = (idx & 31) * 4;
            *(float4*)&Bs[kk][col] = *(const float4*)(W2 + (size_t)(k0 + kk) * 128 + col);
        }
        __syncthreads();
#pragma unroll
        for (int kk = 0; kk < 16; kk++) {
            float av[8], bv[4];
#pragma unroll
            for (int r = 0; r < 8; r++) av[r] = As[kk][w * 8 + r];
#pragma unroll
            for (int c = 0; c < 4; c++) bv[c] = Bs[kk][l + 32 * c];
#pragma unroll
            for (int r = 0; r < 8; r++)
#pragma unroll
                for (int c = 0; c < 4; c++) acc[r][c] += av[r] * bv[c];
        }
        __syncthreads();
    }

    float st[8][4];
    {
        float bias[4];
#pragma unroll
        for (int c = 0; c < 4; c++) bias[c] = hb2[h * 128 + l + 32 * c];
#pragma unroll
        for (int r = 0; r < 8; r++)
#pragma unroll
            for (int c = 0; c < 4; c++) {
                st[r][c] = acc[r][c] + bias[c];
                Ss[w * 8 + r][l + 32 * c] = st[r][c];
            }
    }
    __syncthreads();

    // dyn = state @ dynamics[h]   (K=128)
    float dacc[8][4];
#pragma unroll
    for (int r = 0; r < 8; r++)
#pragma unroll
        for (int c = 0; c < 4; c++) dacc[r][c] = 0.f;

    const float* D = dynm + (size_t)h * 128 * 128;
    for (int k0 = 0; k0 < 128; k0 += 16) {
#pragma unroll
        for (int j = 0; j < 2; j++) {
            int idx = tid + 256 * j;
            int kk = idx >> 5, col = (idx & 31) * 4;
            *(float4*)&Bs[kk][col] = *(const float4*)(D + (size_t)(k0 + kk) * 128 + col);
        }
        __syncthreads();
#pragma unroll
        for (int kk = 0; kk < 16; kk++) {
            float bv[4];
#pragma unroll
            for (int c = 0; c < 4; c++) bv[c] = Bs[kk][l + 32 * c];
#pragma unroll
            for (int r = 0; r < 8; r++) {
                float av = Ss[w * 8 + r][k0 + kk];
#pragma unroll
                for (int c = 0; c < 4; c++) dacc[r][c] += av * bv[c];
            }
        }
        __syncthreads();
    }

    const float invs = 0.08838834764831845f;  // 1/sqrt(128)
#pragma unroll
    for (int r = 0; r < 8; r++) {
        int row = w * 8 + r;
        int t = t0 + row;
        float p = 0.f;
#pragma unroll
        for (int c = 0; c < 4; c++) p += st[r][c] * st[r][c];
        float s2 = warp_sum(p);

        float lgt[8];
        float mx = -1e30f;
#pragma unroll
        for (int a = 0; a < 8; a++) {
            float q = 0.f;
#pragma unroll
            for (int c = 0; c < 4; c++) q += st[r][c] * At[a][l + 32 * c];
            q = warp_sum(q);
            float dd = sqrtf(fmaxf(s2 + a2s[a] - 2.0f * q, 0.0f));
            lgt[a] = -dd * invs;
            mx = fmaxf(mx, lgt[a]);
        }
        float e[8], se = 0.f;
#pragma unroll
        for (int a = 0; a < 8; a++) { e[a] = expf(lgt[a] - mx); se += e[a]; }
        float ise = 1.0f / se;
        float g = g_gate[(size_t)t * 4 + h];
#pragma unroll
        for (int c = 0; c < 4; c++) {
            float ai = 0.f;
#pragma unroll
            for (int a = 0; a < 8; a++) ai += e[a] * At[a][l + 32 * c];
            ai *= ise;
            float sv = st[r][c];
            float outv = sv + g * 0.1f * (ai - sv + tanhf(dacc[r][c]));
            g_comb[(size_t)t * 512 + h * 128 + l + 32 * c] = outv;
        }
    }
}

// ============================================================================
// K4: o1 = gelu(LN(comb @ oW1 + ob1)).  grid T/64, blockDim 512.
// M=64, N=512 (full width so LN is warp-local). warp w rows 4w..4w+3,
// lane l cols l+32j (j=0..15).
// ============================================================================
__global__ void __launch_bounds__(512) k_out1(
    const float* __restrict__ oW1, const float* __restrict__ ob1,
    const float* __restrict__ olg, const float* __restrict__ olb)
{
    int t0 = blockIdx.x * 64;
    __shared__ float As[16][65];
    __shared__ float Bs[16][512];
    __shared__ float sb[512], sg[512], sbb[512];
    int tid = threadIdx.x, w = tid >> 5, l = tid & 31;
    if (tid < 512) { sb[tid] = ob1[tid]; sg[tid] = olg[tid]; sbb[tid] = olb[tid]; }

    float acc[4][16];
#pragma unroll
    for (int r = 0; r < 4; r++)
#pragma unroll
        for (int c = 0; c < 16; c++) acc[r][c] = 0.f;

    int arow = tid >> 3, ac = (tid & 7) * 2;
    for (int k0 = 0; k0 < 512; k0 += 16) {
        float2 a = *(const float2*)(g_comb + (size_t)(t0 + arow) * 512 + k0 + ac);
        As[ac + 0][arow] = a.x; As[ac + 1][arow] = a.y;
#pragma unroll
        for (int j = 0; j < 4; j++) {
            int idx = tid + 512 * j;
            int kk = idx >> 7, col = (idx & 127) * 4;
            *(float4*)&Bs[kk][col] = *(const float4*)(oW1 + (size_t)(k0 + kk) * 512 + col);
        }
        __syncthreads();
#pragma unroll
        for (int kk = 0; kk < 16; kk++) {
            float av[4], bv[16];
#pragma unroll
            for (int r = 0; r < 4; r++) av[r] = As[kk][w * 4 + r];
#pragma unroll
            for (int c = 0; c < 16; c++) bv[c] = Bs[kk][l + 32 * c];
#pragma unroll
            for (int r = 0; r < 4; r++)
#pragma unroll
                for (int c = 0; c < 16; c++) acc[r][c] += av[r] * bv[c];
        }
        __syncthreads();
    }

#pragma unroll
    for (int r = 0; r < 4; r++) {
        int row = w * 4 + r;
        float vv[16];
        float s = 0.f, s2 = 0.f;
#pragma unroll
        for (int c = 0; c < 16; c++) {
            int col = l + 32 * c;
            vv[c] = acc[r][c] + sb[col];
            s += vv[c]; s2 += vv[c] * vv[c];
        }
        s = warp_sum(s); s2 = warp_sum(s2);
        float m = s * (1.0f / 512.0f);
        float var = s2 * (1.0f / 512.0f) - m * m;
        float rs = rsqrtf(var + EPSV);
        float* op = g_oact + (size_t)(t0 + row) * 512;
#pragma unroll
        for (int c = 0; c < 16; c++) {
            int col = l + 32 * c;
            op[col] = gelu_exact((vv[c] - m) * rs * sg[col] + sbb[col]);
        }
    }
}

// ============================================================================
// K5: out = xn + oact @ oW2 + ob2.  grid (T/64, 4), blockDim 256.
// M=64, N=128 per block (col block = blockIdx.y*128).
// ============================================================================
__global__ void __launch_bounds__(256) k_out2(
    const float* __restrict__ oW2, const float* __restrict__ ob2,
    float* __restrict__ out)
{
    int t0 = blockIdx.x * 64;
    int c0 = blockIdx.y * 128;
    __shared__ float As[16][65];
    __shared__ float Bs[16][128];
    int tid = threadIdx.x, w = tid >> 5, l = tid & 31;

    float acc[8][4];
#pragma unroll
    for (int r = 0; r < 8; r++)
#pragma unroll
        for (int c = 0; c < 4; c++) acc[r][c] = 0.f;

    int arow = tid >> 2, ac = (tid & 3) * 4;
    for (int k0 = 0; k0 < 512; k0 += 16) {
        float4 a = *(const float4*)(g_oact + (size_t)(t0 + arow) * 512 + k0 + ac);
        As[ac + 0][arow] = a.x; As[ac + 1][arow] = a.y;
        As[ac + 2][arow] = a.z; As[ac + 3][arow] = a.w;
#pragma unroll
        for (int j = 0; j < 2; j++) {
            int idx = tid + 256 * j;
            int kk = idx >> 5, col = (idx & 31) * 4;
            *(float4*)&Bs[kk][col] =
                *(const float4*)(oW2 + (size_t)(k0 + kk) * 512 + c0 + col);
        }
        __syncthreads();
#pragma unroll
        for (int kk = 0; kk < 16; kk++) {
            float av[8], bv[4];
#pragma unroll
            for (int r = 0; r < 8; r++) av[r] = As[kk][w * 8 + r];
#pragma unroll
            for (int c = 0; c < 4; c++) bv[c] = Bs[kk][l + 32 * c];
#pragma unroll
            for (int r = 0; r < 8; r++)
#pragma unroll
                for (int c = 0; c < 4; c++) acc[r][c] += av[r] * bv[c];
        }
        __syncthreads();
    }

#pragma unroll
    for (int r = 0; r < 8; r++) {
        int row = w * 8 + r;
#pragma unroll
        for (int c = 0; c < 4; c++) {
            int col = c0 + l + 32 * c;
            size_t off = (size_t)(t0 + row) * 512 + col;
            out[off] = acc[r][c] + ob2[col] + g_xn[off];
        }
    }
}

// ============================================================================
extern "C" void kernel_launch(void* const* d_in, const int* in_sizes, int n_in,
                              void* d_out, int out_size)
{
    (void)in_sizes; (void)n_in; (void)out_size;
    const float* x     = (const float*)d_in[0];
    const float* ng    = (const float*)d_in[1];
    const float* nb    = (const float*)d_in[2];
    const float* hW1   = (const float*)d_in[3];
    const float* hb1   = (const float*)d_in[4];
    const float* hlg   = (const float*)d_in[5];
    const float* hlb   = (const float*)d_in[6];
    const float* hW2   = (const float*)d_in[7];
    const float* hb2   = (const float*)d_in[8];
    const float* attr  = (const float*)d_in[9];
    const float* dynm  = (const float*)d_in[10];
    const float* gW    = (const float*)d_in[11];
    const float* gb    = (const float*)d_in[12];
    const float* oW1   = (const float*)d_in[13];
    const float* ob1   = (const float*)d_in[14];
    const float* olg   = (const float*)d_in[15];
    const float* olb   = (const float*)d_in[16];
    const float* oW2   = (const float*)d_in[17];
    const float* ob2   = (const float*)d_in[18];
    float* out = (float*)d_out;

    k_ln_gate<<<8192, 128>>>(x, ng, nb, gW, gb);

    dim3 g2(T_TOK / 64, 4);
    k_head1<<<g2, 256>>>(hW1, hb1, hlg, hlb);
    k_head2<<<g2, 256>>>(hW2, hb2, attr, dynm);

    k_out1<<<T_TOK / 64, 512>>>(oW1, ob1, olg, olb);

    dim3 g5(T_TOK / 64, 4);
    k_out2<<<g5, 256>>>(oW2, ob2, out);
}

// round 3
// speedup vs baseline: 2.2256x; 2.2256x over previous
#include <cuda_runtime.h>
#include <math.h>
#include <stdint.h>

// ----------------------------------------------------------------------------
// NoiseRobustAttractorLayer  (B=16,S=4096,IN=512,HID=512,NH=4,HD=128,NA=8)
// T = 65536 tokens. TF32 tensor-core GEMMs (mma.sync m16n8k8), fp32 accumulate.
// K1: LN(x)->xn ; gate
// K2: h = gelu(LN(xn @ hW1[h] + hb1))        [mma, fused LN over 256]
// K3: state=h@hW2+hb2 ; dyn=state@dynamics ; attractor softmax -> comb
// K4: o1 = gelu(LN(comb @ oW1 + ob1))        [mma, fused LN over 512]
// K5: out = xn + o1 @ oW2 + ob2              [mma, fused residual]
// ----------------------------------------------------------------------------

#define T_TOK 65536
#define EPSV  1e-5f

__device__ float g_xn  [(size_t)T_TOK * 512];
__device__ float g_gate[(size_t)T_TOK * 4];
__device__ float g_h   [(size_t)T_TOK * 1024];
__device__ float g_comb[(size_t)T_TOK * 512];
__device__ float g_oact[(size_t)T_TOK * 512];

__device__ __forceinline__ float warp_sum(float v) {
#pragma unroll
    for (int o = 16; o > 0; o >>= 1) v += __shfl_xor_sync(0xffffffffu, v, o);
    return v;
}
__device__ __forceinline__ float block_sum_128(float v, float* s) {
    v = warp_sum(v);
    int w = threadIdx.x >> 5;
    __syncthreads();
    if ((threadIdx.x & 31) == 0) s[w] = v;
    __syncthreads();
    return s[0] + s[1] + s[2] + s[3];
}
__device__ __forceinline__ float gelu_exact(float x) {
    return 0.5f * x * (1.0f + erff(x * 0.70710678118654752f));
}
__device__ __forceinline__ uint32_t f2tf(float x) {
    uint32_t r; asm("cvt.rna.tf32.f32 %0, %1;" : "=r"(r) : "f"(x)); return r;
}
__device__ __forceinline__ void mma_tf32(float c[4], const uint32_t a[4],
                                         uint32_t b0, uint32_t b1) {
    asm volatile(
        "mma.sync.aligned.m16n8k8.row.col.f32.tf32.tf32.f32 "
        "{%0,%1,%2,%3},{%4,%5,%6,%7},{%8,%9},{%0,%1,%2,%3};"
        : "+f"(c[0]), "+f"(c[1]), "+f"(c[2]), "+f"(c[3])
        : "r"(a[0]), "r"(a[1]), "r"(a[2]), "r"(a[3]), "r"(b0), "r"(b1));
}

// ============================================================================
// K1: layernorm of x + gate logits.
// ============================================================================
__global__ void __launch_bounds__(128) k_ln_gate(
    const float* __restrict__ x, const float* __restrict__ ng,
    const float* __restrict__ nb, const float* __restrict__ gW,
    const float* __restrict__ gb)
{
    __shared__ float sred[4];
    __shared__ float sgW[2048];
    __shared__ float sng[512], snb[512];
    int tid = threadIdx.x;
    for (int i = tid; i < 2048; i += 128) sgW[i] = gW[i];
    for (int i = tid; i < 512; i += 128) { sng[i] = ng[i]; snb[i] = nb[i]; }
    __syncthreads();

    for (int t = blockIdx.x; t < T_TOK; t += gridDim.x) {
        const float* xr = x + (size_t)t * 512;
        float v[4];
#pragma unroll
        for (int j = 0; j < 4; j++) v[j] = xr[tid + 128 * j];
        float s = block_sum_128(v[0] + v[1] + v[2] + v[3], sred);
        float m = s * (1.0f / 512.0f);
        float q = 0.f;
#pragma unroll
        for (int j = 0; j < 4; j++) { float d = v[j] - m; q += d * d; }
        q = block_sum_128(q, sred);
        float rs = rsqrtf(q * (1.0f / 512.0f) + EPSV);
        float xn[4];
#pragma unroll
        for (int j = 0; j < 4; j++) {
            int i = tid + 128 * j;
            xn[j] = (v[j] - m) * rs * sng[i] + snb[i];
            g_xn[(size_t)t * 512 + i] = xn[j];
        }
#pragma unroll
        for (int h = 0; h < 4; h++) {
            float p = 0.f;
#pragma unroll
            for (int j = 0; j < 4; j++) p += xn[j] * sgW[h * 512 + tid + 128 * j];
            p = block_sum_128(p, sred);
            if (tid == 0) g_gate[(size_t)t * 4 + h] = 1.0f / (1.0f + expf(-(p + gb[h])));
        }
    }
}

// ============================================================================
// K2: per-head  h = gelu(LN(xn @ hW1[h] + hb1)).  mma tf32.
// grid (T/64, 4), block 256 (warps 2x4), BM=64, BN=256, BK=16.
// warp tile 32x64: 2 m-subtiles x 8 n-subtiles of m16n8k8.
// ============================================================================
__global__ void __launch_bounds__(256) k_head1_mma(
    const float* __restrict__ hW1, const float* __restrict__ hb1,
    const float* __restrict__ hlg, const float* __restrict__ hlb)
{
    const int h = blockIdx.y;
    const int t0 = blockIdx.x * 64;
    __shared__ uint32_t As[64 * 20];      // stride 20 (conflict-free frags)
    __shared__ uint32_t Bs[16 * 264];     // stride 264 (264%32==8)
    __shared__ float sB[256], sG[256], sBt[256];
    __shared__ float ps[64][4], pq[64][4];
    const int tid = threadIdx.x, w = tid >> 5, l = tid & 31;
    const int wr = w >> 2, wc = w & 3, g = l >> 2, tig = l & 3;

    sB[tid] = hb1[h * 256 + tid]; sG[tid] = hlg[h * 256 + tid]; sBt[tid] = hlb[h * 256 + tid];

    float acc[2][8][4];
#pragma unroll
    for (int mt = 0; mt < 2; mt++)
#pragma unroll
        for (int nt = 0; nt < 8; nt++)
#pragma unroll
            for (int i = 0; i < 4; i++) acc[mt][nt][i] = 0.f;

    const float* Wp = hW1 + (size_t)h * 512 * 256;
    const int ar = tid >> 2, ac4 = (tid & 3) * 4;
    const float* Ap = g_xn + (size_t)(t0 + ar) * 512 + ac4;

    for (int k0 = 0; k0 < 512; k0 += 16) {
        float4 av = *(const float4*)(Ap + k0);
        uint32_t* app = &As[ar * 20 + ac4];
        app[0] = f2tf(av.x); app[1] = f2tf(av.y); app[2] = f2tf(av.z); app[3] = f2tf(av.w);
#pragma unroll
        for (int i = 0; i < 4; i++) {
            int idx = tid + 256 * i;
            int kk = idx >> 6, c4 = (idx & 63) * 4;
            float4 bv = *(const float4*)(Wp + (size_t)(k0 + kk) * 256 + c4);
            uint32_t* bp = &Bs[kk * 264 + c4];
            bp[0] = f2tf(bv.x); bp[1] = f2tf(bv.y); bp[2] = f2tf(bv.z); bp[3] = f2tf(bv.w);
        }
        __syncthreads();
#pragma unroll
        for (int ks = 0; ks < 16; ks += 8) {
            uint32_t af[2][4];
#pragma unroll
            for (int mt = 0; mt < 2; mt++) {
                int rb = (wr * 32 + mt * 16 + g) * 20 + ks;
                af[mt][0] = As[rb + tig];       af[mt][1] = As[rb + 160 + tig];
                af[mt][2] = As[rb + tig + 4];   af[mt][3] = As[rb + 160 + tig + 4];
            }
#pragma unroll
            for (int nt = 0; nt < 8; nt++) {
                int cb = wc * 64 + nt * 8 + g;
                uint32_t b0 = Bs[(ks + tig) * 264 + cb];
                uint32_t b1 = Bs[(ks + tig + 4) * 264 + cb];
                mma_tf32(acc[0][nt], af[0], b0, b1);
                mma_tf32(acc[1][nt], af[1], b0, b1);
            }
        }
        __syncthreads();
    }

    // epilogue: bias + LN(256) + gelu
    float rsm[4] = {0, 0, 0, 0}, rsq[4] = {0, 0, 0, 0};
#pragma unroll
    for (int mt = 0; mt < 2; mt++)
#pragma unroll
        for (int nt = 0; nt < 8; nt++) {
            int c0 = wc * 64 + nt * 8 + 2 * tig;
            float v0 = acc[mt][nt][0] + sB[c0], v1 = acc[mt][nt][1] + sB[c0 + 1];
            float v2 = acc[mt][nt][2] + sB[c0], v3 = acc[mt][nt][3] + sB[c0 + 1];
            acc[mt][nt][0] = v0; acc[mt][nt][1] = v1; acc[mt][nt][2] = v2; acc[mt][nt][3] = v3;
            rsm[mt * 2 + 0] += v0 + v1; rsq[mt * 2 + 0] += v0 * v0 + v1 * v1;
            rsm[mt * 2 + 1] += v2 + v3; rsq[mt * 2 + 1] += v2 * v2 + v3 * v3;
        }
#pragma unroll
    for (int off = 1; off < 4; off <<= 1)
#pragma unroll
        for (int q = 0; q < 4; q++) {
            rsm[q] += __shfl_xor_sync(0xffffffffu, rsm[q], off);
            rsq[q] += __shfl_xor_sync(0xffffffffu, rsq[q], off);
        }
    if (tig == 0) {
#pragma unroll
        for (int q = 0; q < 4; q++) {
            int row = wr * 32 + (q >> 1) * 16 + (q & 1) * 8 + g;
            ps[row][wc] = rsm[q]; pq[row][wc] = rsq[q];
        }
    }
    __syncthreads();
    float mv[4], rv[4];
#pragma unroll
    for (int q = 0; q < 4; q++) {
        int row = wr * 32 + (q >> 1) * 16 + (q & 1) * 8 + g;
        float s  = ps[row][0] + ps[row][1] + ps[row][2] + ps[row][3];
        float s2 = pq[row][0] + pq[row][1] + pq[row][2] + pq[row][3];
        float m = s * (1.f / 256.f);
        float var = s2 * (1.f / 256.f) - m * m;
        mv[q] = m; rv[q] = rsqrtf(var + EPSV);
    }
#pragma unroll
    for (int mt = 0; mt < 2; mt++)
#pragma unroll
        for (int nt = 0; nt < 8; nt++) {
            int c0 = wc * 64 + nt * 8 + 2 * tig;
            int q0 = mt * 2;
            int row0 = t0 + wr * 32 + mt * 16 + g;
            float u0 = gelu_exact((acc[mt][nt][0] - mv[q0]) * rv[q0] * sG[c0] + sBt[c0]);
            float u1 = gelu_exact((acc[mt][nt][1] - mv[q0]) * rv[q0] * sG[c0 + 1] + sBt[c0 + 1]);
            *(float2*)&g_h[(size_t)row0 * 1024 + h * 256 + c0] = make_float2(u0, u1);
            float u2 = gelu_exact((acc[mt][nt][2] - mv[q0 + 1]) * rv[q0 + 1] * sG[c0] + sBt[c0]);
            float u3 = gelu_exact((acc[mt][nt][3] - mv[q0 + 1]) * rv[q0 + 1] * sG[c0 + 1] + sBt[c0 + 1]);
            *(float2*)&g_h[(size_t)(row0 + 8) * 1024 + h * 256 + c0] = make_float2(u2, u3);
        }
}

// ============================================================================
// K3: state GEMM (mma) + dynamics GEMM (mma) + attractor softmax epilogue.
// grid (T/64, 4), block 256 (warps 2x4), BM=64, BN=128.
// dynamic smem: As | Bs | Ss | Dd | At | a2s  (85536 B)
// ============================================================================
#define K3_SMEM 85536
__global__ void __launch_bounds__(256) k_head2_mma(
    const float* __restrict__ hW2, const float* __restrict__ hb2,
    const float* __restrict__ attr, const float* __restrict__ dynm)
{
    extern __shared__ __align__(16) char dsm[];
    uint32_t* As = (uint32_t*)dsm;                 // 64*20*4   = 5120
    uint32_t* Bs = (uint32_t*)(dsm + 5120);        // 16*136*4  = 8704
    float*    Ss = (float*)(dsm + 13824);          // 64*132*4  = 33792
    float*    Dd = (float*)(dsm + 47616);          // 64*132*4  = 33792
    float*    At = (float*)(dsm + 81408);          // 8*128*4   = 4096
    float*   a2s = (float*)(dsm + 85504);          // 8*4

    const int h = blockIdx.y;
    const int t0 = blockIdx.x * 64;
    const int tid = threadIdx.x, w = tid >> 5, l = tid & 31;
    const int wr = w >> 2, wc = w & 3, g = l >> 2, tig = l & 3;

    *(float4*)&At[tid * 4] = *(const float4*)(attr + (size_t)h * 1024 + tid * 4);

    float acc[2][4][4];
#pragma unroll
    for (int mt = 0; mt < 2; mt++)
#pragma unroll
        for (int nt = 0; nt < 4; nt++)
#pragma unroll
            for (int i = 0; i < 4; i++) acc[mt][nt][i] = 0.f;

    const int ar = tid >> 2, ac4 = (tid & 3) * 4;
    const float* Ap = g_h + (size_t)(t0 + ar) * 1024 + h * 256 + ac4;
    const float* Wp = hW2 + (size_t)h * 256 * 128;

    for (int k0 = 0; k0 < 256; k0 += 16) {
        float4 av = *(const float4*)(Ap + k0);
        uint32_t* app = &As[ar * 20 + ac4];
        app[0] = f2tf(av.x); app[1] = f2tf(av.y); app[2] = f2tf(av.z); app[3] = f2tf(av.w);
#pragma unroll
        for (int i = 0; i < 2; i++) {
            int idx = tid + 256 * i;
            int kk = idx >> 5, c4 = (idx & 31) * 4;
            float4 bv = *(const float4*)(Wp + (size_t)(k0 + kk) * 128 + c4);
            uint32_t* bp = &Bs[kk * 136 + c4];
            bp[0] = f2tf(bv.x); bp[1] = f2tf(bv.y); bp[2] = f2tf(bv.z); bp[3] = f2tf(bv.w);
        }
        __syncthreads();
#pragma unroll
        for (int ks = 0; ks < 16; ks += 8) {
            uint32_t af[2][4];
#pragma unroll
            for (int mt = 0; mt < 2; mt++) {
                int rb = (wr * 32 + mt * 16 + g) * 20 + ks;
                af[mt][0] = As[rb + tig];       af[mt][1] = As[rb + 160 + tig];
                af[mt][2] = As[rb + tig + 4];   af[mt][3] = As[rb + 160 + tig + 4];
            }
#pragma unroll
            for (int nt = 0; nt < 4; nt++) {
                int cb = wc * 32 + nt * 8 + g;
                uint32_t b0 = Bs[(ks + tig) * 136 + cb];
                uint32_t b1 = Bs[(ks + tig + 4) * 136 + cb];
                mma_tf32(acc[0][nt], af[0], b0, b1);
                mma_tf32(acc[1][nt], af[1], b0, b1);
            }
        }
        __syncthreads();
    }

    // bias + store state to Ss
#pragma unroll
    for (int mt = 0; mt < 2; mt++)
#pragma unroll
        for (int nt = 0; nt < 4; nt++) {
            int c0 = wc * 32 + nt * 8 + 2 * tig;
            int row = wr * 32 + mt * 16 + g;
            float b0v = hb2[h * 128 + c0], b1v = hb2[h * 128 + c0 + 1];
            Ss[row * 132 + c0]           = acc[mt][nt][0] + b0v;
            Ss[row * 132 + c0 + 1]       = acc[mt][nt][1] + b1v;
            Ss[(row + 8) * 132 + c0]     = acc[mt][nt][2] + b0v;
            Ss[(row + 8) * 132 + c0 + 1] = acc[mt][nt][3] + b1v;
        }
    __syncthreads();

    // dyn = state @ dynamics[h]
    float dcc[2][4][4];
#pragma unroll
    for (int mt = 0; mt < 2; mt++)
#pragma unroll
        for (int nt = 0; nt < 4; nt++)
#pragma unroll
            for (int i = 0; i < 4; i++) dcc[mt][nt][i] = 0.f;

    const float* Dp = dynm + (size_t)h * 128 * 128;
    for (int k0 = 0; k0 < 128; k0 += 16) {
#pragma unroll
        for (int i = 0; i < 2; i++) {
            int idx = tid + 256 * i;
            int kk = idx >> 5, c4 = (idx & 31) * 4;
            float4 bv = *(const float4*)(Dp + (size_t)(k0 + kk) * 128 + c4);
            uint32_t* bp = &Bs[kk * 136 + c4];
            bp[0] = f2tf(bv.x); bp[1] = f2tf(bv.y); bp[2] = f2tf(bv.z); bp[3] = f2tf(bv.w);
        }
        __syncthreads();
#pragma unroll
        for (int ks = 0; ks < 16; ks += 8) {
            uint32_t af[2][4];
#pragma unroll
            for (int mt = 0; mt < 2; mt++) {
                int rb = (wr * 32 + mt * 16 + g) * 132 + k0 + ks;
                af[mt][0] = f2tf(Ss[rb + tig]);
                af[mt][1] = f2tf(Ss[rb + 8 * 132 + tig]);
                af[mt][2] = f2tf(Ss[rb + tig + 4]);
                af[mt][3] = f2tf(Ss[rb + 8 * 132 + tig + 4]);
            }
#pragma unroll
            for (int nt = 0; nt < 4; nt++) {
                int cb = wc * 32 + nt * 8 + g;
                uint32_t b0 = Bs[(ks + tig) * 136 + cb];
                uint32_t b1 = Bs[(ks + tig + 4) * 136 + cb];
                mma_tf32(dcc[0][nt], af[0], b0, b1);
                mma_tf32(dcc[1][nt], af[1], b0, b1);
            }
        }
        __syncthreads();
    }
#pragma unroll
    for (int mt = 0; mt < 2; mt++)
#pragma unroll
        for (int nt = 0; nt < 4; nt++) {
            int c0 = wc * 32 + nt * 8 + 2 * tig;
            int row = wr * 32 + mt * 16 + g;
            Dd[row * 132 + c0]           = dcc[mt][nt][0];
            Dd[row * 132 + c0 + 1]       = dcc[mt][nt][1];
            Dd[(row + 8) * 132 + c0]     = dcc[mt][nt][2];
            Dd[(row + 8) * 132 + c0 + 1] = dcc[mt][nt][3];
        }
    __syncthreads();
    if (tid < 8) {
        float q = 0.f;
#pragma unroll
        for (int k = 0; k < 128; k++) q += At[tid * 128 + k] * At[tid * 128 + k];
        a2s[tid] = q;
    }
    __syncthreads();

    // attractor softmax epilogue: warp w rows w*8..w*8+7, lane l cols l+32c
    const float invs = 0.08838834764831845f;  // 1/sqrt(128)
#pragma unroll
    for (int r = 0; r < 8; r++) {
        int row = w * 8 + r;
        int t = t0 + row;
        float st4[4];
#pragma unroll
        for (int c = 0; c < 4; c++) st4[c] = Ss[row * 132 + l + 32 * c];
        float p = st4[0] * st4[0] + st4[1] * st4[1] + st4[2] * st4[2] + st4[3] * st4[3];
        float s2 = warp_sum(p);

        float lgt[8], mx = -1e30f;
#pragma unroll
        for (int a = 0; a < 8; a++) {
            float q = 0.f;
#pragma unroll
            for (int c = 0; c < 4; c++) q += st4[c] * At[a * 128 + l + 32 * c];
            q = warp_sum(q);
            float dd = sqrtf(fmaxf(s2 + a2s[a] - 2.0f * q, 0.0f));
            lgt[a] = -dd * invs;
            mx = fmaxf(mx, lgt[a]);
        }
        float e[8], se = 0.f;
#pragma unroll
        for (int a = 0; a < 8; a++) { e[a] = expf(lgt[a] - mx); se += e[a]; }
        float ise = 1.0f / se;
        float gt = g_gate[(size_t)t * 4 + h];
#pragma unroll
        for (int c = 0; c < 4; c++) {
            float ai = 0.f;
#pragma unroll
            for (int a = 0; a < 8; a++) ai += e[a] * At[a * 128 + l + 32 * c];
            ai *= ise;
            float sv = st4[c];
            float dv = Dd[row * 132 + l + 32 * c];
            g_comb[(size_t)t * 512 + h * 128 + l + 32 * c] =
                sv + gt * 0.1f * (ai - sv + tanhf(dv));
        }
    }
}

// ============================================================================
// K4: o1 = gelu(LN(comb @ oW1 + ob1)).  mma tf32.
// grid T/64, block 512 (warps 2x8), BM=64, BN=512, BK=16.  static smem 48640B.
// ============================================================================
__global__ void __launch_bounds__(512) k_out1_mma(
    const float* __restrict__ oW1, const float* __restrict__ ob1,
    const float* __restrict__ olg, const float* __restrict__ olb)
{
    __shared__ uint32_t As[64 * 20];       // 5120 B
    __shared__ uint32_t Bs[16 * 520];      // 33280 B (520%32==8)
    __shared__ float sB[512], sG[512], sBt[512];
    __shared__ float ps[64][8], pq[64][8];
    const int t0 = blockIdx.x * 64;
    const int tid = threadIdx.x, w = tid >> 5, l = tid & 31;
    const int wr = w >> 3, wc = w & 7, g = l >> 2, tig = l & 3;

    sB[tid] = ob1[tid]; sG[tid] = olg[tid]; sBt[tid] = olb[tid];

    float acc[2][8][4];
#pragma unroll
    for (int mt = 0; mt < 2; mt++)
#pragma unroll
        for (int nt = 0; nt < 8; nt++)
#pragma unroll
            for (int i = 0; i < 4; i++) acc[mt][nt][i] = 0.f;

    const int ar = tid >> 3, ac2 = (tid & 7) * 2;
    const float* Ap = g_comb + (size_t)(t0 + ar) * 512 + ac2;

    for (int k0 = 0; k0 < 512; k0 += 16) {
        float2 av = *(const float2*)(Ap + k0);
        uint32_t* app = &As[ar * 20 + ac2];
        app[0] = f2tf(av.x); app[1] = f2tf(av.y);
#pragma unroll
        for (int i = 0; i < 4; i++) {
            int idx = tid + 512 * i;
            int kk = idx >> 7, c4 = (idx & 127) * 4;
            float4 bv = *(const float4*)(oW1 + (size_t)(k0 + kk) * 512 + c4);
            uint32_t* bp = &Bs[kk * 520 + c4];
            bp[0] = f2tf(bv.x); bp[1] = f2tf(bv.y); bp[2] = f2tf(bv.z); bp[3] = f2tf(bv.w);
        }
        __syncthreads();
#pragma unroll
        for (int ks = 0; ks < 16; ks += 8) {
            uint32_t af[2][4];
#pragma unroll
            for (int mt = 0; mt < 2; mt++) {
                int rb = (wr * 32 + mt * 16 + g) * 20 + ks;
                af[mt][0] = As[rb + tig];       af[mt][1] = As[rb + 160 + tig];
                af[mt][2] = As[rb + tig + 4];   af[mt][3] = As[rb + 160 + tig + 4];
            }
#pragma unroll
            for (int nt = 0; nt < 8; nt++) {
                int cb = wc * 64 + nt * 8 + g;
                uint32_t b0 = Bs[(ks + tig) * 520 + cb];
                uint32_t b1 = Bs[(ks + tig + 4) * 520 + cb];
                mma_tf32(acc[0][nt], af[0], b0, b1);
                mma_tf32(acc[1][nt], af[1], b0, b1);
            }
        }
        __syncthreads();
    }

    float rsm[4] = {0, 0, 0, 0}, rsq[4] = {0, 0, 0, 0};
#pragma unroll
    for (int mt = 0; mt < 2; mt++)
#pragma unroll
        for (int nt = 0; nt < 8; nt++) {
            int c0 = wc * 64 + nt * 8 + 2 * tig;
            float v0 = acc[mt][nt][0] + sB[c0], v1 = acc[mt][nt][1] + sB[c0 + 1];
            float v2 = acc[mt][nt][2] + sB[c0], v3 = acc[mt][nt][3] + sB[c0 + 1];
            acc[mt][nt][0] = v0; acc[mt][nt][1] = v1; acc[mt][nt][2] = v2; acc[mt][nt][3] = v3;
            rsm[mt * 2 + 0] += v0 + v1; rsq[mt * 2 + 0] += v0 * v0 + v1 * v1;
            rsm[mt * 2 + 1] += v2 + v3; rsq[mt * 2 + 1] += v2 * v2 + v3 * v3;
        }
#pragma unroll
    for (int off = 1; off < 4; off <<= 1)
#pragma unroll
        for (int q = 0; q < 4; q++) {
            rsm[q] += __shfl_xor_sync(0xffffffffu, rsm[q], off);
            rsq[q] += __shfl_xor_sync(0xffffffffu, rsq[q], off);
        }
    if (tig == 0) {
#pragma unroll
        for (int q = 0; q < 4; q++) {
            int row = wr * 32 + (q >> 1) * 16 + (q & 1) * 8 + g;
            ps[row][wc] = rsm[q]; pq[row][wc] = rsq[q];
        }
    }
    __syncthreads();
    float mv[4], rv[4];
#pragma unroll
    for (int q = 0; q < 4; q++) {
        int row = wr * 32 + (q >> 1) * 16 + (q & 1) * 8 + g;
        float s = 0.f, s2 = 0.f;
#pragma unroll
        for (int j = 0; j < 8; j++) { s += ps[row][j]; s2 += pq[row][j]; }
        float m = s * (1.f / 512.f);
        float var = s2 * (1.f / 512.f) - m * m;
        mv[q] = m; rv[q] = rsqrtf(var + EPSV);
    }
#pragma unroll
    for (int mt = 0; mt < 2; mt++)
#pragma unroll
        for (int nt = 0; nt < 8; nt++) {
            int c0 = wc * 64 + nt * 8 + 2 * tig;
            int q0 = mt * 2;
            int row0 = t0 + wr * 32 + mt * 16 + g;
            float u0 = gelu_exact((acc[mt][nt][0] - mv[q0]) * rv[q0] * sG[c0] + sBt[c0]);
            float u1 = gelu_exact((acc[mt][nt][1] - mv[q0]) * rv[q0] * sG[c0 + 1] + sBt[c0 + 1]);
            *(float2*)&g_oact[(size_t)row0 * 512 + c0] = make_float2(u0, u1);
            float u2 = gelu_exact((acc[mt][nt][2] - mv[q0 + 1]) * rv[q0 + 1] * sG[c0] + sBt[c0]);
            float u3 = gelu_exact((acc[mt][nt][3] - mv[q0 + 1]) * rv[q0 + 1] * sG[c0 + 1] + sBt[c0 + 1]);
            *(float2*)&g_oact[(size_t)(row0 + 8) * 512 + c0] = make_float2(u2, u3);
        }
}

// ============================================================================
// K5: out = xn + oact @ oW2 + ob2.  mma tf32.  Same geometry as K4.
// ============================================================================
__global__ void __launch_bounds__(512) k_out2_mma(
    const float* __restrict__ oW2, const float* __restrict__ ob2,
    float* __restrict__ out)
{
    __shared__ uint32_t As[64 * 20];
    __shared__ uint32_t Bs[16 * 520];
    __shared__ float sB[512];
    const int t0 = blockIdx.x * 64;
    const int tid = threadIdx.x, w = tid >> 5, l = tid & 31;
    const int wr = w >> 3, wc = w & 7, g = l >> 2, tig = l & 3;

    sB[tid] = ob2[tid];

    float acc[2][8][4];
#pragma unroll
    for (int mt = 0; mt < 2; mt++)
#pragma unroll
        for (int nt = 0; nt < 8; nt++)
#pragma unroll
            for (int i = 0; i < 4; i++) acc[mt][nt][i] = 0.f;

    const int ar = tid >> 3, ac2 = (tid & 7) * 2;
    const float* Ap = g_oact + (size_t)(t0 + ar) * 512 + ac2;

    for (int k0 = 0; k0 < 512; k0 += 16) {
        float2 av = *(const float2*)(Ap + k0);
        uint32_t* app = &As[ar * 20 + ac2];
        app[0] = f2tf(av.x); app[1] = f2tf(av.y);
#pragma unroll
        for (int i = 0; i < 4; i++) {
            int idx = tid + 512 * i;
            int kk = idx >> 7, c4 = (idx & 127) * 4;
            float4 bv = *(const float4*)(oW2 + (size_t)(k0 + kk) * 512 + c4);
            uint32_t* bp = &Bs[kk * 520 + c4];
            bp[0] = f2tf(bv.x); bp[1] = f2tf(bv.y); bp[2] = f2tf(bv.z); bp[3] = f2tf(bv.w);
        }
        __syncthreads();
#pragma unroll
        for (int ks = 0; ks < 16; ks += 8) {
            uint32_t af[2][4];
#pragma unroll
            for (int mt = 0; mt < 2; mt++) {
                int rb = (wr * 32 + mt * 16 + g) * 20 + ks;
                af[mt][0] = As[rb + tig];       af[mt][1] = As[rb + 160 + tig];
                af[mt][2] = As[rb + tig + 4];   af[mt][3] = As[rb + 160 + tig + 4];
            }
#pragma unroll
            for (int nt = 0; nt < 8; nt++) {
                int cb = wc * 64 + nt * 8 + g;
                uint32_t b0 = Bs[(ks + tig) * 520 + cb];
                uint32_t b1 = Bs[(ks + tig + 4) * 520 + cb];
                mma_tf32(acc[0][nt], af[0], b0, b1);
                mma_tf32(acc[1][nt], af[1], b0, b1);
            }
        }
        __syncthreads();
    }

#pragma unroll
    for (int mt = 0; mt < 2; mt++)
#pragma unroll
        for (int nt = 0; nt < 8; nt++) {
            int c0 = wc * 64 + nt * 8 + 2 * tig;
            int row0 = t0 + wr * 32 + mt * 16 + g;
            size_t o0 = (size_t)row0 * 512 + c0;
            size_t o1 = (size_t)(row0 + 8) * 512 + c0;
            float2 x0 = *(const float2*)&g_xn[o0];
            float2 x1 = *(const float2*)&g_xn[o1];
            *(float2*)&out[o0] = make_float2(acc[mt][nt][0] + sB[c0] + x0.x,
                                             acc[mt][nt][1] + sB[c0 + 1] + x0.y);
            *(float2*)&out[o1] = make_float2(acc[mt][nt][2] + sB[c0] + x1.x,
                                             acc[mt][nt][3] + sB[c0 + 1] + x1.y);
        }
}

// ============================================================================
extern "C" void kernel_launch(void* const* d_in, const int* in_sizes, int n_in,
                              void* d_out, int out_size)
{
    (void)in_sizes; (void)n_in; (void)out_size;
    const float* x    = (const float*)d_in[0];
    const float* ng   = (const float*)d_in[1];
    const float* nb   = (const float*)d_in[2];
    const float* hW1  = (const float*)d_in[3];
    const float* hb1  = (const float*)d_in[4];
    const float* hlg  = (const float*)d_in[5];
    const float* hlb  = (const float*)d_in[6];
    const float* hW2  = (const float*)d_in[7];
    const float* hb2  = (const float*)d_in[8];
    const float* attr = (const float*)d_in[9];
    const float* dynm = (const float*)d_in[10];
    const float* gW   = (const float*)d_in[11];
    const float* gb   = (const float*)d_in[12];
    const float* oW1  = (const float*)d_in[13];
    const float* ob1  = (const float*)d_in[14];
    const float* olg  = (const float*)d_in[15];
    const float* olb  = (const float*)d_in[16];
    const float* oW2  = (const float*)d_in[17];
    const float* ob2  = (const float*)d_in[18];
    float* out = (float*)d_out;

    cudaFuncSetAttribute(k_head2_mma, cudaFuncAttributeMaxDynamicSharedMemorySize, K3_SMEM);

    k_ln_gate<<<8192, 128>>>(x, ng, nb, gW, gb);

    dim3 gh(T_TOK / 64, 4);
    k_head1_mma<<<gh, 256>>>(hW1, hb1, hlg, hlb);
    k_head2_mma<<<gh, 256, K3_SMEM>>>(hW2, hb2, attr, dynm);

    k_out1_mma<<<T_TOK / 64, 512>>>(oW1, ob1, olg, olb);
    k_out2_mma<<<T_TOK / 64, 512>>>(oW2, ob2, out);
}

// round 4
// speedup vs baseline: 2.6767x; 1.2027x over previous
#include <cuda_runtime.h>
#include <math.h>
#include <stdint.h>

// ----------------------------------------------------------------------------
// NoiseRobustAttractorLayer — TF32 mma.sync GEMMs + cp.async double buffering.
// Weights pre-converted to tf32 once per launch; activations stored tf32-
// rounded where consumed as GEMM-A (bit-identical to load-time cvt).
// ----------------------------------------------------------------------------

#define T_TOK 65536
#define EPSV  1e-5f

__device__ float g_xn  [(size_t)T_TOK * 512];   // fp32 (residual)
__device__ float g_xnt [(size_t)T_TOK * 512];   // tf32-rounded (GEMM A)
__device__ float g_gate[(size_t)T_TOK * 4];
__device__ float g_h   [(size_t)T_TOK * 1024];  // tf32-rounded
__device__ float g_comb[(size_t)T_TOK * 512];   // tf32-rounded
__device__ float g_oact[(size_t)T_TOK * 512];   // tf32-rounded

// pre-converted weights (tf32 bit patterns stored as float)
__device__ float g_hW1t[4 * 512 * 256];   // 524288
__device__ float g_hW2t[4 * 256 * 128];   // 131072
__device__ float g_dynt[4 * 128 * 128];   //  65536
__device__ float g_oW1t[512 * 512];       // 262144
__device__ float g_oW2t[512 * 512];       // 262144

__device__ __forceinline__ float warp_sum(float v) {
#pragma unroll
    for (int o = 16; o > 0; o >>= 1) v += __shfl_xor_sync(0xffffffffu, v, o);
    return v;
}
__device__ __forceinline__ float block_sum_128(float v, float* s) {
    v = warp_sum(v);
    int w = threadIdx.x >> 5;
    __syncthreads();
    if ((threadIdx.x & 31) == 0) s[w] = v;
    __syncthreads();
    return s[0] + s[1] + s[2] + s[3];
}
__device__ __forceinline__ float gelu_exact(float x) {
    return 0.5f * x * (1.0f + erff(x * 0.70710678118654752f));
}
__device__ __forceinline__ uint32_t f2tf(float x) {
    uint32_t r; asm("cvt.rna.tf32.f32 %0, %1;" : "=r"(r) : "f"(x)); return r;
}
__device__ __forceinline__ float f2tf_f(float x) {
    return __uint_as_float(f2tf(x));
}
__device__ __forceinline__ void mma_tf32(float c[4], const uint32_t a[4],
                                         uint32_t b0, uint32_t b1) {
    asm volatile(
        "mma.sync.aligned.m16n8k8.row.col.f32.tf32.tf32.f32 "
        "{%0,%1,%2,%3},{%4,%5,%6,%7},{%8,%9},{%0,%1,%2,%3};"
        : "+f"(c[0]), "+f"(c[1]), "+f"(c[2]), "+f"(c[3])
        : "r"(a[0]), "r"(a[1]), "r"(a[2]), "r"(a[3]), "r"(b0), "r"(b1));
}
__device__ __forceinline__ void cp16(void* s, const void* g) {
    uint32_t sa = (uint32_t)__cvta_generic_to_shared(s);
    asm volatile("cp.async.cg.shared.global [%0], [%1], 16;" :: "r"(sa), "l"(g));
}
#define CP_COMMIT()   asm volatile("cp.async.commit_group;")
#define CP_WAIT_ALL() asm volatile("cp.async.wait_group 0;" ::: "memory")

// ============================================================================
// K0: weight pre-conversion fp32 -> tf32 (1,245,184 elements)
// ============================================================================
__global__ void __launch_bounds__(256) k_prep(
    const float* __restrict__ hW1, const float* __restrict__ hW2,
    const float* __restrict__ dynm, const float* __restrict__ oW1,
    const float* __restrict__ oW2)
{
    int i = blockIdx.x * 256 + threadIdx.x;
    if (i < 524288)       g_hW1t[i]           = f2tf_f(hW1[i]);
    else if (i < 655360)  g_hW2t[i - 524288]  = f2tf_f(hW2[i - 524288]);
    else if (i < 720896)  g_dynt[i - 655360]  = f2tf_f(dynm[i - 655360]);
    else if (i < 983040)  g_oW1t[i - 720896]  = f2tf_f(oW1[i - 720896]);
    else if (i < 1245184) g_oW2t[i - 983040]  = f2tf_f(oW2[i - 983040]);
}

// ============================================================================
// K1: layernorm of x + gate logits (+ tf32 copy of xn)
// ============================================================================
__global__ void __launch_bounds__(128) k_ln_gate(
    const float* __restrict__ x, const float* __restrict__ ng,
    const float* __restrict__ nb, const float* __restrict__ gW,
    const float* __restrict__ gb)
{
    __shared__ float sred[4];
    __shared__ float sgW[2048];
    __shared__ float sng[512], snb[512];
    int tid = threadIdx.x;
    for (int i = tid; i < 2048; i += 128) sgW[i] = gW[i];
    for (int i = tid; i < 512; i += 128) { sng[i] = ng[i]; snb[i] = nb[i]; }
    __syncthreads();

    for (int t = blockIdx.x; t < T_TOK; t += gridDim.x) {
        const float* xr = x + (size_t)t * 512;
        float v[4];
#pragma unroll
        for (int j = 0; j < 4; j++) v[j] = xr[tid + 128 * j];
        float s = block_sum_128(v[0] + v[1] + v[2] + v[3], sred);
        float m = s * (1.0f / 512.0f);
        float q = 0.f;
#pragma unroll
        for (int j = 0; j < 4; j++) { float d = v[j] - m; q += d * d; }
        q = block_sum_128(q, sred);
        float rs = rsqrtf(q * (1.0f / 512.0f) + EPSV);
        float xn[4];
#pragma unroll
        for (int j = 0; j < 4; j++) {
            int i = tid + 128 * j;
            xn[j] = (v[j] - m) * rs * sng[i] + snb[i];
            g_xn [(size_t)t * 512 + i] = xn[j];
            g_xnt[(size_t)t * 512 + i] = f2tf_f(xn[j]);
        }
#pragma unroll
        for (int h = 0; h < 4; h++) {
            float p = 0.f;
#pragma unroll
            for (int j = 0; j < 4; j++) p += xn[j] * sgW[h * 512 + tid + 128 * j];
            p = block_sum_128(p, sred);
            if (tid == 0) g_gate[(size_t)t * 4 + h] = 1.0f / (1.0f + expf(-(p + gb[h])));
        }
    }
}

// ============================================================================
// K2: h = gelu(LN(xn @ hW1[h] + hb1)).  cp.async 2-stage, BM=64,BN=256,BK=16.
// dyn smem: As 2*64*20 | Bs 2*16*264 | sB sG sBt | ps pq   = 49152 B
// ============================================================================
#define K2_SMEM 49152
__global__ void __launch_bounds__(256) k_head1_mma(
    const float* __restrict__ hb1,
    const float* __restrict__ hlg, const float* __restrict__ hlb)
{
    extern __shared__ __align__(16) char dsm[];
    uint32_t* As = (uint32_t*)dsm;                 // +0     10240
    uint32_t* Bs = (uint32_t*)(dsm + 10240);       //        33792
    float* sB  = (float*)(dsm + 44032);
    float* sG  = (float*)(dsm + 45056);
    float* sBt = (float*)(dsm + 46080);
    float* ps  = (float*)(dsm + 47104);            // 64*4
    float* pq  = (float*)(dsm + 48128);            // 64*4

    const int h = blockIdx.y;
    const int t0 = blockIdx.x * 64;
    const int tid = threadIdx.x, w = tid >> 5, l = tid & 31;
    const int wr = w >> 2, wc = w & 3, g = l >> 2, tig = l & 3;

    sB[tid] = hb1[h * 256 + tid]; sG[tid] = hlg[h * 256 + tid]; sBt[tid] = hlb[h * 256 + tid];

    float acc[2][8][4];
#pragma unroll
    for (int mt = 0; mt < 2; mt++)
#pragma unroll
        for (int nt = 0; nt < 8; nt++)
#pragma unroll
            for (int i = 0; i < 4; i++) acc[mt][nt][i] = 0.f;

    const float* Wp = g_hW1t + (size_t)h * 512 * 256;
    const int ar = tid >> 2, ac4 = (tid & 3) * 4;
    const float* Ap = g_xnt + (size_t)(t0 + ar) * 512 + ac4;

    // stage loader
    auto load_stage = [&](int s, int k0) {
        cp16(&As[s * 1280 + ar * 20 + ac4], Ap + k0);
#pragma unroll
        for (int i = 0; i < 4; i++) {
            int idx = tid + 256 * i;
            int kk = idx >> 6, c4 = (idx & 63) * 4;
            cp16(&Bs[s * 4224 + kk * 264 + c4], Wp + (size_t)(k0 + kk) * 256 + c4);
        }
    };

    load_stage(0, 0); CP_COMMIT();
    for (int it = 0; it < 32; it++) {
        const int cur = it & 1;
        CP_WAIT_ALL();
        __syncthreads();
        if (it + 1 < 32) { load_stage(cur ^ 1, (it + 1) * 16); CP_COMMIT(); }
        const uint32_t* Ab = &As[cur * 1280];
        const uint32_t* Bb = &Bs[cur * 4224];
#pragma unroll
        for (int ks = 0; ks < 16; ks += 8) {
            uint32_t af[2][4];
#pragma unroll
            for (int mt = 0; mt < 2; mt++) {
                int rb = (wr * 32 + mt * 16 + g) * 20 + ks;
                af[mt][0] = Ab[rb + tig];       af[mt][1] = Ab[rb + 160 + tig];
                af[mt][2] = Ab[rb + tig + 4];   af[mt][3] = Ab[rb + 160 + tig + 4];
            }
#pragma unroll
            for (int nt = 0; nt < 8; nt++) {
                int cb = wc * 64 + nt * 8 + g;
                uint32_t b0 = Bb[(ks + tig) * 264 + cb];
                uint32_t b1 = Bb[(ks + tig + 4) * 264 + cb];
                mma_tf32(acc[0][nt], af[0], b0, b1);
                mma_tf32(acc[1][nt], af[1], b0, b1);
            }
        }
        __syncthreads();
    }

    // epilogue: bias + LN(256) + gelu ; store tf32-rounded
    float rsm[4] = {0, 0, 0, 0}, rsq[4] = {0, 0, 0, 0};
#pragma unroll
    for (int mt = 0; mt < 2; mt++)
#pragma unroll
        for (int nt = 0; nt < 8; nt++) {
            int c0 = wc * 64 + nt * 8 + 2 * tig;
            float v0 = acc[mt][nt][0] + sB[c0], v1 = acc[mt][nt][1] + sB[c0 + 1];
            float v2 = acc[mt][nt][2] + sB[c0], v3 = acc[mt][nt][3] + sB[c0 + 1];
            acc[mt][nt][0] = v0; acc[mt][nt][1] = v1; acc[mt][nt][2] = v2; acc[mt][nt][3] = v3;
            rsm[mt * 2 + 0] += v0 + v1; rsq[mt * 2 + 0] += v0 * v0 + v1 * v1;
            rsm[mt * 2 + 1] += v2 + v3; rsq[mt * 2 + 1] += v2 * v2 + v3 * v3;
        }
#pragma unroll
    for (int off = 1; off < 4; off <<= 1)
#pragma unroll
        for (int q = 0; q < 4; q++) {
            rsm[q] += __shfl_xor_sync(0xffffffffu, rsm[q], off);
            rsq[q] += __shfl_xor_sync(0xffffffffu, rsq[q], off);
        }
    if (tig == 0) {
#pragma unroll
        for (int q = 0; q < 4; q++) {
            int row = wr * 32 + (q >> 1) * 16 + (q & 1) * 8 + g;
            ps[row * 4 + wc] = rsm[q]; pq[row * 4 + wc] = rsq[q];
        }
    }
    __syncthreads();
    float mv[4], rv[4];
#pragma unroll
    for (int q = 0; q < 4; q++) {
        int row = wr * 32 + (q >> 1) * 16 + (q & 1) * 8 + g;
        float s  = ps[row * 4 + 0] + ps[row * 4 + 1] + ps[row * 4 + 2] + ps[row * 4 + 3];
        float s2 = pq[row * 4 + 0] + pq[row * 4 + 1] + pq[row * 4 + 2] + pq[row * 4 + 3];
        float m = s * (1.f / 256.f);
        float var = s2 * (1.f / 256.f) - m * m;
        mv[q] = m; rv[q] = rsqrtf(var + EPSV);
    }
#pragma unroll
    for (int mt = 0; mt < 2; mt++)
#pragma unroll
        for (int nt = 0; nt < 8; nt++) {
            int c0 = wc * 64 + nt * 8 + 2 * tig;
            int q0 = mt * 2;
            int row0 = t0 + wr * 32 + mt * 16 + g;
            float u0 = gelu_exact((acc[mt][nt][0] - mv[q0]) * rv[q0] * sG[c0] + sBt[c0]);
            float u1 = gelu_exact((acc[mt][nt][1] - mv[q0]) * rv[q0] * sG[c0 + 1] + sBt[c0 + 1]);
            *(float2*)&g_h[(size_t)row0 * 1024 + h * 256 + c0] =
                make_float2(f2tf_f(u0), f2tf_f(u1));
            float u2 = gelu_exact((acc[mt][nt][2] - mv[q0 + 1]) * rv[q0 + 1] * sG[c0] + sBt[c0]);
            float u3 = gelu_exact((acc[mt][nt][3] - mv[q0 + 1]) * rv[q0 + 1] * sG[c0 + 1] + sBt[c0 + 1]);
            *(float2*)&g_h[(size_t)(row0 + 8) * 1024 + h * 256 + c0] =
                make_float2(f2tf_f(u2), f2tf_f(u3));
        }
}

// ============================================================================
// K3: state GEMM + dynamics GEMM + attractor softmax.  cp.async on state GEMM.
// dyn smem: As | Bs | Ss | Dd | At | a2s = 99360 B
// ============================================================================
#define K3_SMEM 99360
__global__ void __launch_bounds__(256) k_head2_mma(
    const float* __restrict__ hb2, const float* __restrict__ attr)
{
    extern __shared__ __align__(16) char dsm[];
    uint32_t* As = (uint32_t*)dsm;                 // +0     10240 (2*64*20)
    uint32_t* Bs = (uint32_t*)(dsm + 10240);       //        17408 (2*16*136)
    float*    Ss = (float*)(dsm + 27648);          //        33792 (64*132)
    float*    Dd = (float*)(dsm + 61440);          //        33792
    float*    At = (float*)(dsm + 95232);          //         4096
    float*   a2s = (float*)(dsm + 99328);          //           32

    const int h = blockIdx.y;
    const int t0 = blockIdx.x * 64;
    const int tid = threadIdx.x, w = tid >> 5, l = tid & 31;
    const int wr = w >> 2, wc = w & 3, g = l >> 2, tig = l & 3;

    *(float4*)&At[tid * 4] = *(const float4*)(attr + (size_t)h * 1024 + tid * 4);

    float acc[2][4][4];
#pragma unroll
    for (int mt = 0; mt < 2; mt++)
#pragma unroll
        for (int nt = 0; nt < 4; nt++)
#pragma unroll
            for (int i = 0; i < 4; i++) acc[mt][nt][i] = 0.f;

    const int ar = tid >> 2, ac4 = (tid & 3) * 4;
    const float* Ap = g_h + (size_t)(t0 + ar) * 1024 + h * 256 + ac4;
    const float* Wp = g_hW2t + (size_t)h * 256 * 128;

    auto load_stage = [&](int s, int k0) {
        cp16(&As[s * 1280 + ar * 20 + ac4], Ap + k0);
#pragma unroll
        for (int i = 0; i < 2; i++) {
            int idx = tid + 256 * i;
            int kk = idx >> 5, c4 = (idx & 31) * 4;
            cp16(&Bs[s * 2176 + kk * 136 + c4], Wp + (size_t)(k0 + kk) * 128 + c4);
        }
    };

    load_stage(0, 0); CP_COMMIT();
    for (int it = 0; it < 16; it++) {
        const int cur = it & 1;
        CP_WAIT_ALL();
        __syncthreads();
        if (it + 1 < 16) { load_stage(cur ^ 1, (it + 1) * 16); CP_COMMIT(); }
        const uint32_t* Ab = &As[cur * 1280];
        const uint32_t* Bb = &Bs[cur * 2176];
#pragma unroll
        for (int ks = 0; ks < 16; ks += 8) {
            uint32_t af[2][4];
#pragma unroll
            for (int mt = 0; mt < 2; mt++) {
                int rb = (wr * 32 + mt * 16 + g) * 20 + ks;
                af[mt][0] = Ab[rb + tig];       af[mt][1] = Ab[rb + 160 + tig];
                af[mt][2] = Ab[rb + tig + 4];   af[mt][3] = Ab[rb + 160 + tig + 4];
            }
#pragma unroll
            for (int nt = 0; nt < 4; nt++) {
                int cb = wc * 32 + nt * 8 + g;
                uint32_t b0 = Bb[(ks + tig) * 136 + cb];
                uint32_t b1 = Bb[(ks + tig + 4) * 136 + cb];
                mma_tf32(acc[0][nt], af[0], b0, b1);
                mma_tf32(acc[1][nt], af[1], b0, b1);
            }
        }
        __syncthreads();
    }

    // bias + store state to Ss
#pragma unroll
    for (int mt = 0; mt < 2; mt++)
#pragma unroll
        for (int nt = 0; nt < 4; nt++) {
            int c0 = wc * 32 + nt * 8 + 2 * tig;
            int row = wr * 32 + mt * 16 + g;
            float b0v = hb2[h * 128 + c0], b1v = hb2[h * 128 + c0 + 1];
            Ss[row * 132 + c0]           = acc[mt][nt][0] + b0v;
            Ss[row * 132 + c0 + 1]       = acc[mt][nt][1] + b1v;
            Ss[(row + 8) * 132 + c0]     = acc[mt][nt][2] + b0v;
            Ss[(row + 8) * 132 + c0 + 1] = acc[mt][nt][3] + b1v;
        }
    __syncthreads();

    // dyn = state @ dynamics[h]  (weights pre-converted, no cvt)
    float dcc[2][4][4];
#pragma unroll
    for (int mt = 0; mt < 2; mt++)
#pragma unroll
        for (int nt = 0; nt < 4; nt++)
#pragma unroll
            for (int i = 0; i < 4; i++) dcc[mt][nt][i] = 0.f;

    const float* Dp = g_dynt + (size_t)h * 128 * 128;
    for (int k0 = 0; k0 < 128; k0 += 16) {
#pragma unroll
        for (int i = 0; i < 2; i++) {
            int idx = tid + 256 * i;
            int kk = idx >> 5, c4 = (idx & 31) * 4;
            float4 bv = *(const float4*)(Dp + (size_t)(k0 + kk) * 128 + c4);
            uint32_t* bp = &Bs[kk * 136 + c4];
            bp[0] = __float_as_uint(bv.x); bp[1] = __float_as_uint(bv.y);
            bp[2] = __float_as_uint(bv.z); bp[3] = __float_as_uint(bv.w);
        }
        __syncthreads();
#pragma unroll
        for (int ks = 0; ks < 16; ks += 8) {
            uint32_t af[2][4];
#pragma unroll
            for (int mt = 0; mt < 2; mt++) {
                int rb = (wr * 32 + mt * 16 + g) * 132 + k0 + ks;
                af[mt][0] = f2tf(Ss[rb + tig]);
                af[mt][1] = f2tf(Ss[rb + 8 * 132 + tig]);
                af[mt][2] = f2tf(Ss[rb + tig + 4]);
                af[mt][3] = f2tf(Ss[rb + 8 * 132 + tig + 4]);
            }
#pragma unroll
            for (int nt = 0; nt < 4; nt++) {
                int cb = wc * 32 + nt * 8 + g;
                uint32_t b0 = Bs[(ks + tig) * 136 + cb];
                uint32_t b1 = Bs[(ks + tig + 4) * 136 + cb];
                mma_tf32(dcc[0][nt], af[0], b0, b1);
                mma_tf32(dcc[1][nt], af[1], b0, b1);
            }
        }
        __syncthreads();
    }
#pragma unroll
    for (int mt = 0; mt < 2; mt++)
#pragma unroll
        for (int nt = 0; nt < 4; nt++) {
            int c0 = wc * 32 + nt * 8 + 2 * tig;
            int row = wr * 32 + mt * 16 + g;
            Dd[row * 132 + c0]           = dcc[mt][nt][0];
            Dd[row * 132 + c0 + 1]       = dcc[mt][nt][1];
            Dd[(row + 8) * 132 + c0]     = dcc[mt][nt][2];
            Dd[(row + 8) * 132 + c0 + 1] = dcc[mt][nt][3];
        }
    __syncthreads();
    if (tid < 8) {
        float q = 0.f;
#pragma unroll
        for (int k = 0; k < 128; k++) q += At[tid * 128 + k] * At[tid * 128 + k];
        a2s[tid] = q;
    }
    __syncthreads();

    const float invs = 0.08838834764831845f;  // 1/sqrt(128)
#pragma unroll
    for (int r = 0; r < 8; r++) {
        int row = w * 8 + r;
        int t = t0 + row;
        float st4[4];
#pragma unroll
        for (int c = 0; c < 4; c++) st4[c] = Ss[row * 132 + l + 32 * c];
        float p = st4[0] * st4[0] + st4[1] * st4[1] + st4[2] * st4[2] + st4[3] * st4[3];
        float s2 = warp_sum(p);

        float lgt[8], mx = -1e30f;
#pragma unroll
        for (int a = 0; a < 8; a++) {
            float q = 0.f;
#pragma unroll
            for (int c = 0; c < 4; c++) q += st4[c] * At[a * 128 + l + 32 * c];
            q = warp_sum(q);
            float dd = sqrtf(fmaxf(s2 + a2s[a] - 2.0f * q, 0.0f));
            lgt[a] = -dd * invs;
            mx = fmaxf(mx, lgt[a]);
        }
        float e[8], se = 0.f;
#pragma unroll
        for (int a = 0; a < 8; a++) { e[a] = expf(lgt[a] - mx); se += e[a]; }
        float ise = 1.0f / se;
        float gt = g_gate[(size_t)t * 4 + h];
#pragma unroll
        for (int c = 0; c < 4; c++) {
            float ai = 0.f;
#pragma unroll
            for (int a = 0; a < 8; a++) ai += e[a] * At[a * 128 + l + 32 * c];
            ai *= ise;
            float sv = st4[c];
            float dv = Dd[row * 132 + l + 32 * c];
            g_comb[(size_t)t * 512 + h * 128 + l + 32 * c] =
                f2tf_f(sv + gt * 0.1f * (ai - sv + tanhf(dv)));
        }
    }
}

// ============================================================================
// K4: o1 = gelu(LN(comb @ oW1 + ob1)).  BM=64,BN=512, block 512, cp.async.
// dyn smem: As 10240 | Bs 66560 | sB sG sBt 6144 | ps pq 4096 = 87040 B
// ============================================================================
#define K4_SMEM 87040
__global__ void __launch_bounds__(512) k_out1_mma(
    const float* __restrict__ ob1,
    const float* __restrict__ olg, const float* __restrict__ olb)
{
    extern __shared__ __align__(16) char dsm[];
    uint32_t* As = (uint32_t*)dsm;                 // 2*64*20
    uint32_t* Bs = (uint32_t*)(dsm + 10240);       // 2*16*520
    float* sB  = (float*)(dsm + 76800);
    float* sG  = (float*)(dsm + 78848);
    float* sBt = (float*)(dsm + 80896);
    float* ps  = (float*)(dsm + 82944);            // 64*8
    float* pq  = (float*)(dsm + 84992);

    const int t0 = blockIdx.x * 64;
    const int tid = threadIdx.x, w = tid >> 5, l = tid & 31;
    const int wr = w >> 3, wc = w & 7, g = l >> 2, tig = l & 3;

    sB[tid] = ob1[tid]; sG[tid] = olg[tid]; sBt[tid] = olb[tid];

    float acc[2][8][4];
#pragma unroll
    for (int mt = 0; mt < 2; mt++)
#pragma unroll
        for (int nt = 0; nt < 8; nt++)
#pragma unroll
            for (int i = 0; i < 4; i++) acc[mt][nt][i] = 0.f;

    const int ar = tid >> 2, ac4 = (tid & 3) * 4;  // valid when tid<256
    const float* Ap = g_comb + (size_t)(t0 + (ar & 63)) * 512 + ac4;

    auto load_stage = [&](int s, int k0) {
        if (tid < 256) cp16(&As[s * 1280 + ar * 20 + ac4], Ap + k0);
#pragma unroll
        for (int i = 0; i < 4; i++) {
            int idx = tid + 512 * i;
            int kk = idx >> 7, c4 = (idx & 127) * 4;
            cp16(&Bs[s * 8320 + kk * 520 + c4], g_oW1t + (size_t)(k0 + kk) * 512 + c4);
        }
    };

    load_stage(0, 0); CP_COMMIT();
    for (int it = 0; it < 32; it++) {
        const int cur = it & 1;
        CP_WAIT_ALL();
        __syncthreads();
        if (it + 1 < 32) { load_stage(cur ^ 1, (it + 1) * 16); CP_COMMIT(); }
        const uint32_t* Ab = &As[cur * 1280];
        const uint32_t* Bb = &Bs[cur * 8320];
#pragma unroll
        for (int ks = 0; ks < 16; ks += 8) {
            uint32_t af[2][4];
#pragma unroll
            for (int mt = 0; mt < 2; mt++) {
                int rb = (wr * 32 + mt * 16 + g) * 20 + ks;
                af[mt][0] = Ab[rb + tig];       af[mt][1] = Ab[rb + 160 + tig];
                af[mt][2] = Ab[rb + tig + 4];   af[mt][3] = Ab[rb + 160 + tig + 4];
            }
#pragma unroll
            for (int nt = 0; nt < 8; nt++) {
                int cb = wc * 64 + nt * 8 + g;
                uint32_t b0 = Bb[(ks + tig) * 520 + cb];
                uint32_t b1 = Bb[(ks + tig + 4) * 520 + cb];
                mma_tf32(acc[0][nt], af[0], b0, b1);
                mma_tf32(acc[1][nt], af[1], b0, b1);
            }
        }
        __syncthreads();
    }

    float rsm[4] = {0, 0, 0, 0}, rsq[4] = {0, 0, 0, 0};
#pragma unroll
    for (int mt = 0; mt < 2; mt++)
#pragma unroll
        for (int nt = 0; nt < 8; nt++) {
            int c0 = wc * 64 + nt * 8 + 2 * tig;
            float v0 = acc[mt][nt][0] + sB[c0], v1 = acc[mt][nt][1] + sB[c0 + 1];
            float v2 = acc[mt][nt][2] + sB[c0], v3 = acc[mt][nt][3] + sB[c0 + 1];
            acc[mt][nt][0] = v0; acc[mt][nt][1] = v1; acc[mt][nt][2] = v2; acc[mt][nt][3] = v3;
            rsm[mt * 2 + 0] += v0 + v1; rsq[mt * 2 + 0] += v0 * v0 + v1 * v1;
            rsm[mt * 2 + 1] += v2 + v3; rsq[mt * 2 + 1] += v2 * v2 + v3 * v3;
        }
#pragma unroll
    for (int off = 1; off < 4; off <<= 1)
#pragma unroll
        for (int q = 0; q < 4; q++) {
            rsm[q] += __shfl_xor_sync(0xffffffffu, rsm[q], off);
            rsq[q] += __shfl_xor_sync(0xffffffffu, rsq[q], off);
        }
    if (tig == 0) {
#pragma unroll
        for (int q = 0; q < 4; q++) {
            int row = wr * 32 + (q >> 1) * 16 + (q & 1) * 8 + g;
            ps[row * 8 + wc] = rsm[q]; pq[row * 8 + wc] = rsq[q];
        }
    }
    __syncthreads();
    float mv[4], rv[4];
#pragma unroll
    for (int q = 0; q < 4; q++) {
        int row = wr * 32 + (q >> 1) * 16 + (q & 1) * 8 + g;
        float s = 0.f, s2 = 0.f;
#pragma unroll
        for (int j = 0; j < 8; j++) { s += ps[row * 8 + j]; s2 += pq[row * 8 + j]; }
        float m = s * (1.f / 512.f);
        float var = s2 * (1.f / 512.f) - m * m;
        mv[q] = m; rv[q] = rsqrtf(var + EPSV);
    }
#pragma unroll
    for (int mt = 0; mt < 2; mt++)
#pragma unroll
        for (int nt = 0; nt < 8; nt++) {
            int c0 = wc * 64 + nt * 8 + 2 * tig;
            int q0 = mt * 2;
            int row0 = t0 + wr * 32 + mt * 16 + g;
            float u0 = gelu_exact((acc[mt][nt][0] - mv[q0]) * rv[q0] * sG[c0] + sBt[c0]);
            float u1 = gelu_exact((acc[mt][nt][1] - mv[q0]) * rv[q0] * sG[c0 + 1] + sBt[c0 + 1]);
            *(float2*)&g_oact[(size_t)row0 * 512 + c0] = make_float2(f2tf_f(u0), f2tf_f(u1));
            float u2 = gelu_exact((acc[mt][nt][2] - mv[q0 + 1]) * rv[q0 + 1] * sG[c0] + sBt[c0]);
            float u3 = gelu_exact((acc[mt][nt][3] - mv[q0 + 1]) * rv[q0 + 1] * sG[c0 + 1] + sBt[c0 + 1]);
            *(float2*)&g_oact[(size_t)(row0 + 8) * 512 + c0] = make_float2(f2tf_f(u2), f2tf_f(u3));
        }
}

// ============================================================================
// K5: out = xn + oact @ oW2 + ob2.  Same geometry as K4.
// dyn smem: As 10240 | Bs 66560 | sB 2048 = 78848 B
// ============================================================================
#define K5_SMEM 78848
__global__ void __launch_bounds__(512) k_out2_mma(
    const float* __restrict__ ob2, float* __restrict__ out)
{
    extern __shared__ __align__(16) char dsm[];
    uint32_t* As = (uint32_t*)dsm;
    uint32_t* Bs = (uint32_t*)(dsm + 10240);
    float* sB = (float*)(dsm + 76800);

    const int t0 = blockIdx.x * 64;
    const int tid = threadIdx.x, w = tid >> 5, l = tid & 31;
    const int wr = w >> 3, wc = w & 7, g = l >> 2, tig = l & 3;

    sB[tid] = ob2[tid];

    float acc[2][8][4];
#pragma unroll
    for (int mt = 0; mt < 2; mt++)
#pragma unroll
        for (int nt = 0; nt < 8; nt++)
#pragma unroll
            for (int i = 0; i < 4; i++) acc[mt][nt][i] = 0.f;

    const int ar = tid >> 2, ac4 = (tid & 3) * 4;
    const float* Ap = g_oact + (size_t)(t0 + (ar & 63)) * 512 + ac4;

    auto load_stage = [&](int s, int k0) {
        if (tid < 256) cp16(&As[s * 1280 + ar * 20 + ac4], Ap + k0);
#pragma unroll
        for (int i = 0; i < 4; i++) {
            int idx = tid + 512 * i;
            int kk = idx >> 7, c4 = (idx & 127) * 4;
            cp16(&Bs[s * 8320 + kk * 520 + c4], g_oW2t + (size_t)(k0 + kk) * 512 + c4);
        }
    };

    load_stage(0, 0); CP_COMMIT();
    for (int it = 0; it < 32; it++) {
        const int cur = it & 1;
        CP_WAIT_ALL();
        __syncthreads();
        if (it + 1 < 32) { load_stage(cur ^ 1, (it + 1) * 16); CP_COMMIT(); }
        const uint32_t* Ab = &As[cur * 1280];
        const uint32_t* Bb = &Bs[cur * 8320];
#pragma unroll
        for (int ks = 0; ks < 16; ks += 8) {
            uint32_t af[2][4];
#pragma unroll
            for (int mt = 0; mt < 2; mt++) {
                int rb = (wr * 32 + mt * 16 + g) * 20 + ks;
                af[mt][0] = Ab[rb + tig];       af[mt][1] = Ab[rb + 160 + tig];
                af[mt][2] = Ab[rb + tig + 4];   af[mt][3] = Ab[rb + 160 + tig + 4];
            }
#pragma unroll
            for (int nt = 0; nt < 8; nt++) {
                int cb = wc * 64 + nt * 8 + g;
                uint32_t b0 = Bb[(ks + tig) * 520 + cb];
                uint32_t b1 = Bb[(ks + tig + 4) * 520 + cb];
                mma_tf32(acc[0][nt], af[0], b0, b1);
                mma_tf32(acc[1][nt], af[1], b0, b1);
            }
        }
        __syncthreads();
    }

#pragma unroll
    for (int mt = 0; mt < 2; mt++)
#pragma unroll
        for (int nt = 0; nt < 8; nt++) {
            int c0 = wc * 64 + nt * 8 + 2 * tig;
            int row0 = t0 + wr * 32 + mt * 16 + g;
            size_t o0 = (size_t)row0 * 512 + c0;
            size_t o1 = (size_t)(row0 + 8) * 512 + c0;
            float2 x0 = *(const float2*)&g_xn[o0];
            float2 x1 = *(const float2*)&g_xn[o1];
            *(float2*)&out[o0] = make_float2(acc[mt][nt][0] + sB[c0] + x0.x,
                                             acc[mt][nt][1] + sB[c0 + 1] + x0.y);
            *(float2*)&out[o1] = make_float2(acc[mt][nt][2] + sB[c0] + x1.x,
                                             acc[mt][nt][3] + sB[c0 + 1] + x1.y);
        }
}

// ============================================================================
extern "C" void kernel_launch(void* const* d_in, const int* in_sizes, int n_in,
                              void* d_out, int out_size)
{
    (void)in_sizes; (void)n_in; (void)out_size;
    const float* x    = (const float*)d_in[0];
    const float* ng   = (const float*)d_in[1];
    const float* nb   = (const float*)d_in[2];
    const float* hW1  = (const float*)d_in[3];
    const float* hb1  = (const float*)d_in[4];
    const float* hlg  = (const float*)d_in[5];
    const float* hlb  = (const float*)d_in[6];
    const float* hW2  = (const float*)d_in[7];
    const float* hb2  = (const float*)d_in[8];
    const float* attr = (const float*)d_in[9];
    const float* dynm = (const float*)d_in[10];
    const float* gW   = (const float*)d_in[11];
    const float* gb   = (const float*)d_in[12];
    const float* oW1  = (const float*)d_in[13];
    const float* ob1  = (const float*)d_in[14];
    const float* olg  = (const float*)d_in[15];
    const float* olb  = (const float*)d_in[16];
    const float* oW2  = (const float*)d_in[17];
    const float* ob2  = (const float*)d_in[18];
    float* out = (float*)d_out;

    static bool attr_set = false;
    if (!attr_set) {
        cudaFuncSetAttribute(k_head1_mma, cudaFuncAttributeMaxDynamicSharedMemorySize, K2_SMEM);
        cudaFuncSetAttribute(k_head2_mma, cudaFuncAttributeMaxDynamicSharedMemorySize, K3_SMEM);
        cudaFuncSetAttribute(k_out1_mma,  cudaFuncAttributeMaxDynamicSharedMemorySize, K4_SMEM);
        cudaFuncSetAttribute(k_out2_mma,  cudaFuncAttributeMaxDynamicSharedMemorySize, K5_SMEM);
        attr_set = true;
    }

    k_prep<<<4864, 256>>>(hW1, hW2, dynm, oW1, oW2);
    k_ln_gate<<<8192, 128>>>(x, ng, nb, gW, gb);

    dim3 gh(T_TOK / 64, 4);
    k_head1_mma<<<gh, 256, K2_SMEM>>>(hb1, hlg, hlb);
    k_head2_mma<<<gh, 256, K3_SMEM>>>(hb2, attr);

    k_out1_mma<<<T_TOK / 64, 512, K4_SMEM>>>(ob1, olg, olb);
    k_out2_mma<<<T_TOK / 64, 512, K5_SMEM>>>(ob2, out);
}

// round 5
// speedup vs baseline: 2.9184x; 1.0903x over previous
#include <cuda_runtime.h>
#include <math.h>
#include <stdint.h>

// ----------------------------------------------------------------------------
// NoiseRobustAttractorLayer — TF32 mma.sync GEMMs + cp.async double buffering.
// R5: k_head2 rewritten — attractor dots fused into the dynamics MMA sweep,
// state stored tf32 in smem (no cvt on A frags), Dd buffer dropped (75KB smem,
// 2 CTAs/SM).
// ----------------------------------------------------------------------------

#define T_TOK 65536
#define EPSV  1e-5f

__device__ float g_xn  [(size_t)T_TOK * 512];   // fp32 (residual)
__device__ float g_xnt [(size_t)T_TOK * 512];   // tf32-rounded (GEMM A)
__device__ float g_gate[(size_t)T_TOK * 4];
__device__ float g_h   [(size_t)T_TOK * 1024];  // tf32-rounded
__device__ float g_comb[(size_t)T_TOK * 512];   // tf32-rounded
__device__ float g_oact[(size_t)T_TOK * 512];   // tf32-rounded

// pre-converted weights (tf32 bit patterns stored as float)
__device__ float g_hW1t[4 * 512 * 256];
__device__ float g_hW2t[4 * 256 * 128];
__device__ float g_dynt[4 * 128 * 128];
__device__ float g_oW1t[512 * 512];
__device__ float g_oW2t[512 * 512];

__device__ __forceinline__ float warp_sum(float v) {
#pragma unroll
    for (int o = 16; o > 0; o >>= 1) v += __shfl_xor_sync(0xffffffffu, v, o);
    return v;
}
__device__ __forceinline__ float block_sum_128(float v, float* s) {
    v = warp_sum(v);
    int w = threadIdx.x >> 5;
    __syncthreads();
    if ((threadIdx.x & 31) == 0) s[w] = v;
    __syncthreads();
    return s[0] + s[1] + s[2] + s[3];
}
__device__ __forceinline__ float gelu_exact(float x) {
    return 0.5f * x * (1.0f + erff(x * 0.70710678118654752f));
}
__device__ __forceinline__ uint32_t f2tf(float x) {
    uint32_t r; asm("cvt.rna.tf32.f32 %0, %1;" : "=r"(r) : "f"(x)); return r;
}
__device__ __forceinline__ float f2tf_f(float x) {
    return __uint_as_float(f2tf(x));
}
__device__ __forceinline__ void mma_tf32(float c[4], const uint32_t a[4],
                                         uint32_t b0, uint32_t b1) {
    asm volatile(
        "mma.sync.aligned.m16n8k8.row.col.f32.tf32.tf32.f32 "
        "{%0,%1,%2,%3},{%4,%5,%6,%7},{%8,%9},{%0,%1,%2,%3};"
        : "+f"(c[0]), "+f"(c[1]), "+f"(c[2]), "+f"(c[3])
        : "r"(a[0]), "r"(a[1]), "r"(a[2]), "r"(a[3]), "r"(b0), "r"(b1));
}
__device__ __forceinline__ void cp16(void* s, const void* g) {
    uint32_t sa = (uint32_t)__cvta_generic_to_shared(s);
    asm volatile("cp.async.cg.shared.global [%0], [%1], 16;" :: "r"(sa), "l"(g));
}
#define CP_COMMIT()   asm volatile("cp.async.commit_group;")
#define CP_WAIT_ALL() asm volatile("cp.async.wait_group 0;" ::: "memory")

// ============================================================================
// K0: weight pre-conversion fp32 -> tf32
// ============================================================================
__global__ void __launch_bounds__(256) k_prep(
    const float* __restrict__ hW1, const float* __restrict__ hW2,
    const float* __restrict__ dynm, const float* __restrict__ oW1,
    const float* __restrict__ oW2)
{
    int i = blockIdx.x * 256 + threadIdx.x;
    if (i < 524288)       g_hW1t[i]           = f2tf_f(hW1[i]);
    else if (i < 655360)  g_hW2t[i - 524288]  = f2tf_f(hW2[i - 524288]);
    else if (i < 720896)  g_dynt[i - 655360]  = f2tf_f(dynm[i - 655360]);
    else if (i < 983040)  g_oW1t[i - 720896]  = f2tf_f(oW1[i - 720896]);
    else if (i < 1245184) g_oW2t[i - 983040]  = f2tf_f(oW2[i - 983040]);
}

// ============================================================================
// K1: layernorm of x + gate logits (+ tf32 copy of xn)
// ============================================================================
__global__ void __launch_bounds__(128) k_ln_gate(
    const float* __restrict__ x, const float* __restrict__ ng,
    const float* __restrict__ nb, const float* __restrict__ gW,
    const float* __restrict__ gb)
{
    __shared__ float sred[4];
    __shared__ float sgW[2048];
    __shared__ float sng[512], snb[512];
    int tid = threadIdx.x;
    for (int i = tid; i < 2048; i += 128) sgW[i] = gW[i];
    for (int i = tid; i < 512; i += 128) { sng[i] = ng[i]; snb[i] = nb[i]; }
    __syncthreads();

    for (int t = blockIdx.x; t < T_TOK; t += gridDim.x) {
        const float* xr = x + (size_t)t * 512;
        float v[4];
#pragma unroll
        for (int j = 0; j < 4; j++) v[j] = xr[tid + 128 * j];
        float s = block_sum_128(v[0] + v[1] + v[2] + v[3], sred);
        float m = s * (1.0f / 512.0f);
        float q = 0.f;
#pragma unroll
        for (int j = 0; j < 4; j++) { float d = v[j] - m; q += d * d; }
        q = block_sum_128(q, sred);
        float rs = rsqrtf(q * (1.0f / 512.0f) + EPSV);
        float xn[4];
#pragma unroll
        for (int j = 0; j < 4; j++) {
            int i = tid + 128 * j;
            xn[j] = (v[j] - m) * rs * sng[i] + snb[i];
            g_xn [(size_t)t * 512 + i] = xn[j];
            g_xnt[(size_t)t * 512 + i] = f2tf_f(xn[j]);
        }
#pragma unroll
        for (int h = 0; h < 4; h++) {
            float p = 0.f;
#pragma unroll
            for (int j = 0; j < 4; j++) p += xn[j] * sgW[h * 512 + tid + 128 * j];
            p = block_sum_128(p, sred);
            if (tid == 0) g_gate[(size_t)t * 4 + h] = 1.0f / (1.0f + expf(-(p + gb[h])));
        }
    }
}

// ============================================================================
// K2: h = gelu(LN(xn @ hW1[h] + hb1)).  cp.async 2-stage, BM=64,BN=256,BK=16.
// ============================================================================
#define K2_SMEM 49152
__global__ void __launch_bounds__(256) k_head1_mma(
    const float* __restrict__ hb1,
    const float* __restrict__ hlg, const float* __restrict__ hlb)
{
    extern __shared__ __align__(16) char dsm[];
    uint32_t* As = (uint32_t*)dsm;                 // +0     10240
    uint32_t* Bs = (uint32_t*)(dsm + 10240);       //        33792
    float* sB  = (float*)(dsm + 44032);
    float* sG  = (float*)(dsm + 45056);
    float* sBt = (float*)(dsm + 46080);
    float* ps  = (float*)(dsm + 47104);            // 64*4
    float* pq  = (float*)(dsm + 48128);            // 64*4

    const int h = blockIdx.y;
    const int t0 = blockIdx.x * 64;
    const int tid = threadIdx.x, w = tid >> 5, l = tid & 31;
    const int wr = w >> 2, wc = w & 3, g = l >> 2, tig = l & 3;

    sB[tid] = hb1[h * 256 + tid]; sG[tid] = hlg[h * 256 + tid]; sBt[tid] = hlb[h * 256 + tid];

    float acc[2][8][4];
#pragma unroll
    for (int mt = 0; mt < 2; mt++)
#pragma unroll
        for (int nt = 0; nt < 8; nt++)
#pragma unroll
            for (int i = 0; i < 4; i++) acc[mt][nt][i] = 0.f;

    const float* Wp = g_hW1t + (size_t)h * 512 * 256;
    const int ar = tid >> 2, ac4 = (tid & 3) * 4;
    const float* Ap = g_xnt + (size_t)(t0 + ar) * 512 + ac4;

    auto load_stage = [&](int s, int k0) {
        cp16(&As[s * 1280 + ar * 20 + ac4], Ap + k0);
#pragma unroll
        for (int i = 0; i < 4; i++) {
            int idx = tid + 256 * i;
            int kk = idx >> 6, c4 = (idx & 63) * 4;
            cp16(&Bs[s * 4224 + kk * 264 + c4], Wp + (size_t)(k0 + kk) * 256 + c4);
        }
    };

    load_stage(0, 0); CP_COMMIT();
    for (int it = 0; it < 32; it++) {
        const int cur = it & 1;
        CP_WAIT_ALL();
        __syncthreads();
        if (it + 1 < 32) { load_stage(cur ^ 1, (it + 1) * 16); CP_COMMIT(); }
        const uint32_t* Ab = &As[cur * 1280];
        const uint32_t* Bb = &Bs[cur * 4224];
#pragma unroll
        for (int ks = 0; ks < 16; ks += 8) {
            uint32_t af[2][4];
#pragma unroll
            for (int mt = 0; mt < 2; mt++) {
                int rb = (wr * 32 + mt * 16 + g) * 20 + ks;
                af[mt][0] = Ab[rb + tig];       af[mt][1] = Ab[rb + 160 + tig];
                af[mt][2] = Ab[rb + tig + 4];   af[mt][3] = Ab[rb + 160 + tig + 4];
            }
#pragma unroll
            for (int nt = 0; nt < 8; nt++) {
                int cb = wc * 64 + nt * 8 + g;
                uint32_t b0 = Bb[(ks + tig) * 264 + cb];
                uint32_t b1 = Bb[(ks + tig + 4) * 264 + cb];
                mma_tf32(acc[0][nt], af[0], b0, b1);
                mma_tf32(acc[1][nt], af[1], b0, b1);
            }
        }
        __syncthreads();
    }

    // epilogue: bias + LN(256) + gelu ; store tf32-rounded
    float rsm[4] = {0, 0, 0, 0}, rsq[4] = {0, 0, 0, 0};
#pragma unroll
    for (int mt = 0; mt < 2; mt++)
#pragma unroll
        for (int nt = 0; nt < 8; nt++) {
            int c0 = wc * 64 + nt * 8 + 2 * tig;
            float v0 = acc[mt][nt][0] + sB[c0], v1 = acc[mt][nt][1] + sB[c0 + 1];
            float v2 = acc[mt][nt][2] + sB[c0], v3 = acc[mt][nt][3] + sB[c0 + 1];
            acc[mt][nt][0] = v0; acc[mt][nt][1] = v1; acc[mt][nt][2] = v2; acc[mt][nt][3] = v3;
            rsm[mt * 2 + 0] += v0 + v1; rsq[mt * 2 + 0] += v0 * v0 + v1 * v1;
            rsm[mt * 2 + 1] += v2 + v3; rsq[mt * 2 + 1] += v2 * v2 + v3 * v3;
        }
#pragma unroll
    for (int off = 1; off < 4; off <<= 1)
#pragma unroll
        for (int q = 0; q < 4; q++) {
            rsm[q] += __shfl_xor_sync(0xffffffffu, rsm[q], off);
            rsq[q] += __shfl_xor_sync(0xffffffffu, rsq[q], off);
        }
    if (tig == 0) {
#pragma unroll
        for (int q = 0; q < 4; q++) {
            int row = wr * 32 + (q >> 1) * 16 + (q & 1) * 8 + g;
            ps[row * 4 + wc] = rsm[q]; pq[row * 4 + wc] = rsq[q];
        }
    }
    __syncthreads();
    float mv[4], rv[4];
#pragma unroll
    for (int q = 0; q < 4; q++) {
        int row = wr * 32 + (q >> 1) * 16 + (q & 1) * 8 + g;
        float s  = ps[row * 4 + 0] + ps[row * 4 + 1] + ps[row * 4 + 2] + ps[row * 4 + 3];
        float s2 = pq[row * 4 + 0] + pq[row * 4 + 1] + pq[row * 4 + 2] + pq[row * 4 + 3];
        float m = s * (1.f / 256.f);
        float var = s2 * (1.f / 256.f) - m * m;
        mv[q] = m; rv[q] = rsqrtf(var + EPSV);
    }
#pragma unroll
    for (int mt = 0; mt < 2; mt++)
#pragma unroll
        for (int nt = 0; nt < 8; nt++) {
            int c0 = wc * 64 + nt * 8 + 2 * tig;
            int q0 = mt * 2;
            int row0 = t0 + wr * 32 + mt * 16 + g;
            float u0 = gelu_exact((acc[mt][nt][0] - mv[q0]) * rv[q0] * sG[c0] + sBt[c0]);
            float u1 = gelu_exact((acc[mt][nt][1] - mv[q0]) * rv[q0] * sG[c0 + 1] + sBt[c0 + 1]);
            *(float2*)&g_h[(size_t)row0 * 1024 + h * 256 + c0] =
                make_float2(f2tf_f(u0), f2tf_f(u1));
            float u2 = gelu_exact((acc[mt][nt][2] - mv[q0 + 1]) * rv[q0 + 1] * sG[c0] + sBt[c0]);
            float u3 = gelu_exact((acc[mt][nt][3] - mv[q0 + 1]) * rv[q0 + 1] * sG[c0 + 1] + sBt[c0 + 1]);
            *(float2*)&g_h[(size_t)(row0 + 8) * 1024 + h * 256 + c0] =
                make_float2(f2tf_f(u2), f2tf_f(u3));
        }
}

// ============================================================================
// K3 (v2): state GEMM -> Ss(tf32) ; [dynamics | attractors] fused GEMM ;
// per-row softmax ; mix from registers.  75040 B dyn smem, 2 CTAs/SM.
// ============================================================================
#define K3_SMEM 75040
__global__ void __launch_bounds__(256, 2) k_head2_mma(
    const float* __restrict__ hb2, const float* __restrict__ attr)
{
    extern __shared__ __align__(16) char dsm[];
    uint32_t* As  = (uint32_t*)dsm;                // 10240 (2*64*20)
    uint32_t* Bs  = (uint32_t*)(dsm + 10240);      // 17408 (2*16*136)
    float*    Ss  = (float*)(dsm + 27648);         // 33792 (64*132) tf32 bits
    float*    At  = (float*)(dsm + 61440);         //  4096 (8*128) fp32
    uint32_t* AtT = (uint32_t*)(dsm + 65536);      //  4096 (128*8) tf32
    float*    Sa  = (float*)(dsm + 69632);         //  2048 (64*8)
    float*    Sw  = (float*)(dsm + 71680);         //  2048 (64*8)
    float*    s2p = (float*)(dsm + 73728);         //  1024 (64*4)
    float*    a2s = (float*)(dsm + 74752);         //    32
    float*    Sgt = (float*)(dsm + 74784);         //   256 (64)

    const int h = blockIdx.y;
    const int t0 = blockIdx.x * 64;
    const int tid = threadIdx.x, w = tid >> 5, l = tid & 31;
    const int wr = w >> 2, wc = w & 3, g = l >> 2, tig = l & 3;

    // attractors: fp32 copy + transposed tf32 copy (B operand for sa columns)
    {
        float4 v = *(const float4*)(attr + (size_t)h * 1024 + tid * 4);
        *(float4*)&At[tid * 4] = v;
        int a0 = tid >> 5, d0 = (tid & 31) * 4;   // v = At[a0][d0..d0+3]
        AtT[(d0 + 0) * 8 + a0] = f2tf(v.x);
        AtT[(d0 + 1) * 8 + a0] = f2tf(v.y);
        AtT[(d0 + 2) * 8 + a0] = f2tf(v.z);
        AtT[(d0 + 3) * 8 + a0] = f2tf(v.w);
    }

    // ---- phase 1: state = h @ hW2[h]  (cp.async 2-stage) ----
    float acc[2][4][4];
#pragma unroll
    for (int mt = 0; mt < 2; mt++)
#pragma unroll
        for (int nt = 0; nt < 4; nt++)
#pragma unroll
            for (int i = 0; i < 4; i++) acc[mt][nt][i] = 0.f;

    const int ar = tid >> 2, ac4 = (tid & 3) * 4;
    const float* Ap = g_h + (size_t)(t0 + ar) * 1024 + h * 256 + ac4;
    const float* Wp = g_hW2t + (size_t)h * 256 * 128;

    auto load_stage1 = [&](int s, int k0) {
        cp16(&As[s * 1280 + ar * 20 + ac4], Ap + k0);
#pragma unroll
        for (int i = 0; i < 2; i++) {
            int idx = tid + 256 * i;
            int kk = idx >> 5, c4 = (idx & 31) * 4;
            cp16(&Bs[s * 2176 + kk * 136 + c4], Wp + (size_t)(k0 + kk) * 128 + c4);
        }
    };

    load_stage1(0, 0); CP_COMMIT();
    __syncthreads();
    if (tid < 8) {   // ||a||^2 (fp32, tiny)
        float q = 0.f;
#pragma unroll
        for (int k = 0; k < 128; k++) q += At[tid * 128 + k] * At[tid * 128 + k];
        a2s[tid] = q;
    }

    for (int it = 0; it < 16; it++) {
        const int cur = it & 1;
        CP_WAIT_ALL();
        __syncthreads();
        if (it + 1 < 16) { load_stage1(cur ^ 1, (it + 1) * 16); CP_COMMIT(); }
        const uint32_t* Ab = &As[cur * 1280];
        const uint32_t* Bb = &Bs[cur * 2176];
#pragma unroll
        for (int ks = 0; ks < 16; ks += 8) {
            uint32_t af[2][4];
#pragma unroll
            for (int mt = 0; mt < 2; mt++) {
                int rb = (wr * 32 + mt * 16 + g) * 20 + ks;
                af[mt][0] = Ab[rb + tig];       af[mt][1] = Ab[rb + 160 + tig];
                af[mt][2] = Ab[rb + tig + 4];   af[mt][3] = Ab[rb + 160 + tig + 4];
            }
#pragma unroll
            for (int nt = 0; nt < 4; nt++) {
                int cb = wc * 32 + nt * 8 + g;
                uint32_t b0 = Bb[(ks + tig) * 136 + cb];
                uint32_t b1 = Bb[(ks + tig + 4) * 136 + cb];
                mma_tf32(acc[0][nt], af[0], b0, b1);
                mma_tf32(acc[1][nt], af[1], b0, b1);
            }
        }
        __syncthreads();
    }

    // epilogue 1: bias, tf32-round, store Ss, accumulate ||s||^2 partials
    {
        float rq[4] = {0, 0, 0, 0};
#pragma unroll
        for (int mt = 0; mt < 2; mt++)
#pragma unroll
            for (int nt = 0; nt < 4; nt++) {
                int c0 = wc * 32 + nt * 8 + 2 * tig;
                int row = wr * 32 + mt * 16 + g;
                float b0v = hb2[h * 128 + c0], b1v = hb2[h * 128 + c0 + 1];
                float v0 = f2tf_f(acc[mt][nt][0] + b0v);
                float v1 = f2tf_f(acc[mt][nt][1] + b1v);
                float v2 = f2tf_f(acc[mt][nt][2] + b0v);
                float v3 = f2tf_f(acc[mt][nt][3] + b1v);
                Ss[row * 132 + c0]           = v0;
                Ss[row * 132 + c0 + 1]       = v1;
                Ss[(row + 8) * 132 + c0]     = v2;
                Ss[(row + 8) * 132 + c0 + 1] = v3;
                rq[mt * 2 + 0] += v0 * v0 + v1 * v1;
                rq[mt * 2 + 1] += v2 * v2 + v3 * v3;
            }
#pragma unroll
        for (int off = 1; off < 4; off <<= 1)
#pragma unroll
            for (int q = 0; q < 4; q++)
                rq[q] += __shfl_xor_sync(0xffffffffu, rq[q], off);
        if (tig == 0) {
#pragma unroll
            for (int q = 0; q < 4; q++) {
                int row = wr * 32 + (q >> 1) * 16 + (q & 1) * 8 + g;
                s2p[row * 4 + wc] = rq[q];
            }
        }
    }
    __syncthreads();

    // ---- phase 2: [dyn | sa] = state @ [dynamics[h] | attr^T]  (N=128+8) ----
    float dcc[2][4][4];
    float scc[2][4];
#pragma unroll
    for (int mt = 0; mt < 2; mt++) {
#pragma unroll
        for (int nt = 0; nt < 4; nt++)
#pragma unroll
            for (int i = 0; i < 4; i++) dcc[mt][nt][i] = 0.f;
#pragma unroll
        for (int i = 0; i < 4; i++) scc[mt][i] = 0.f;
    }

    const float* Dp = g_dynt + (size_t)h * 128 * 128;
    auto load_stage2 = [&](int s, int k0) {
#pragma unroll
        for (int i = 0; i < 2; i++) {
            int idx = tid + 256 * i;
            int kk = idx >> 5, c4 = (idx & 31) * 4;
            cp16(&Bs[s * 2176 + kk * 136 + c4], Dp + (size_t)(k0 + kk) * 128 + c4);
        }
    };

    load_stage2(0, 0); CP_COMMIT();
    for (int it = 0; it < 8; it++) {
        const int cur = it & 1;
        CP_WAIT_ALL();
        __syncthreads();
        if (it + 1 < 8) { load_stage2(cur ^ 1, (it + 1) * 16); CP_COMMIT(); }
        const uint32_t* Bb = &Bs[cur * 2176];
        const int kbase = it * 16;
#pragma unroll
        for (int ks = 0; ks < 16; ks += 8) {
            uint32_t af[2][4];
#pragma unroll
            for (int mt = 0; mt < 2; mt++) {
                int rb = (wr * 32 + mt * 16 + g) * 132 + kbase + ks;
                af[mt][0] = __float_as_uint(Ss[rb + tig]);
                af[mt][1] = __float_as_uint(Ss[rb + 8 * 132 + tig]);
                af[mt][2] = __float_as_uint(Ss[rb + tig + 4]);
                af[mt][3] = __float_as_uint(Ss[rb + 8 * 132 + tig + 4]);
            }
#pragma unroll
            for (int nt = 0; nt < 4; nt++) {
                int cb = wc * 32 + nt * 8 + g;
                uint32_t b0 = Bb[(ks + tig) * 136 + cb];
                uint32_t b1 = Bb[(ks + tig + 4) * 136 + cb];
                mma_tf32(dcc[0][nt], af[0], b0, b1);
                mma_tf32(dcc[1][nt], af[1], b0, b1);
            }
            // sa columns (attractor dots) — same A frags, B from AtT
            uint32_t b0s = AtT[(kbase + ks + tig) * 8 + g];
            uint32_t b1s = AtT[(kbase + ks + tig + 4) * 8 + g];
            mma_tf32(scc[0], af[0], b0s, b1s);
            mma_tf32(scc[1], af[1], b0s, b1s);
        }
        __syncthreads();
    }

    // write sa (all warps computed identical copies; wc==0 writes)
    if (wc == 0) {
#pragma unroll
        for (int mt = 0; mt < 2; mt++) {
            int row = wr * 32 + mt * 16 + g;
            Sa[row * 8 + 2 * tig]           = scc[mt][0];
            Sa[row * 8 + 2 * tig + 1]       = scc[mt][1];
            Sa[(row + 8) * 8 + 2 * tig]     = scc[mt][2];
            Sa[(row + 8) * 8 + 2 * tig + 1] = scc[mt][3];
        }
    }
    __syncthreads();

    // per-row softmax over 8 attractors (one thread per row)
    const float invs = 0.08838834764831845f;  // 1/sqrt(128)
    if (tid < 64) {
        int row = tid;
        float s2 = s2p[row * 4 + 0] + s2p[row * 4 + 1] + s2p[row * 4 + 2] + s2p[row * 4 + 3];
        float lgt[8], mx = -1e30f;
#pragma unroll
        for (int a = 0; a < 8; a++) {
            float dd = sqrtf(fmaxf(s2 + a2s[a] - 2.0f * Sa[row * 8 + a], 0.0f));
            lgt[a] = -dd * invs;
            mx = fmaxf(mx, lgt[a]);
        }
        float e[8], se = 0.f;
#pragma unroll
        for (int a = 0; a < 8; a++) { e[a] = expf(lgt[a] - mx); se += e[a]; }
        float ise = 1.0f / se;
#pragma unroll
        for (int a = 0; a < 8; a++) Sw[row * 8 + a] = e[a] * ise;
        Sgt[row] = 0.1f * g_gate[(size_t)(t0 + row) * 4 + h];
    }
    __syncthreads();

    // final mix: out = s + 0.1*gate*(attr_infl - s + tanh(dyn))
#pragma unroll
    for (int mt = 0; mt < 2; mt++)
#pragma unroll
        for (int nt = 0; nt < 4; nt++) {
            int c0 = wc * 32 + nt * 8 + 2 * tig;
#pragma unroll
            for (int half = 0; half < 2; half++) {
                int row = wr * 32 + mt * 16 + g + 8 * half;
                float gt = Sgt[row];
                float sv0 = Ss[row * 132 + c0];
                float sv1 = Ss[row * 132 + c0 + 1];
                float ai0 = 0.f, ai1 = 0.f;
#pragma unroll
                for (int a = 0; a < 8; a++) {
                    float wgt = Sw[row * 8 + a];
                    ai0 += wgt * At[a * 128 + c0];
                    ai1 += wgt * At[a * 128 + c0 + 1];
                }
                float dv0 = dcc[mt][nt][2 * half + 0];
                float dv1 = dcc[mt][nt][2 * half + 1];
                float o0 = f2tf_f(sv0 + gt * (ai0 - sv0 + tanhf(dv0)));
                float o1 = f2tf_f(sv1 + gt * (ai1 - sv1 + tanhf(dv1)));
                *(float2*)&g_comb[(size_t)(t0 + row) * 512 + h * 128 + c0] =
                    make_float2(o0, o1);
            }
        }
}

// ============================================================================
// K4: o1 = gelu(LN(comb @ oW1 + ob1)).  BM=64,BN=512, block 512, cp.async.
// ============================================================================
#define K4_SMEM 87040
__global__ void __launch_bounds__(512) k_out1_mma(
    const float* __restrict__ ob1,
    const float* __restrict__ olg, const float* __restrict__ olb)
{
    extern __shared__ __align__(16) char dsm[];
    uint32_t* As = (uint32_t*)dsm;                 // 2*64*20
    uint32_t* Bs = (uint32_t*)(dsm + 10240);       // 2*16*520
    float* sB  = (float*)(dsm + 76800);
    float* sG  = (float*)(dsm + 78848);
    float* sBt = (float*)(dsm + 80896);
    float* ps  = (float*)(dsm + 82944);            // 64*8
    float* pq  = (float*)(dsm + 84992);

    const int t0 = blockIdx.x * 64;
    const int tid = threadIdx.x, w = tid >> 5, l = tid & 31;
    const int wr = w >> 3, wc = w & 7, g = l >> 2, tig = l & 3;

    sB[tid] = ob1[tid]; sG[tid] = olg[tid]; sBt[tid] = olb[tid];

    float acc[2][8][4];
#pragma unroll
    for (int mt = 0; mt < 2; mt++)
#pragma unroll
        for (int nt = 0; nt < 8; nt++)
#pragma unroll
            for (int i = 0; i < 4; i++) acc[mt][nt][i] = 0.f;

    const int ar = tid >> 2, ac4 = (tid & 3) * 4;
    const float* Ap = g_comb + (size_t)(t0 + (ar & 63)) * 512 + ac4;

    auto load_stage = [&](int s, int k0) {
        if (tid < 256) cp16(&As[s * 1280 + ar * 20 + ac4], Ap + k0);
#pragma unroll
        for (int i = 0; i < 4; i++) {
            int idx = tid + 512 * i;
            int kk = idx >> 7, c4 = (idx & 127) * 4;
            cp16(&Bs[s * 8320 + kk * 520 + c4], g_oW1t + (size_t)(k0 + kk) * 512 + c4);
        }
    };

    load_stage(0, 0); CP_COMMIT();
    for (int it = 0; it < 32; it++) {
        const int cur = it & 1;
        CP_WAIT_ALL();
        __syncthreads();
        if (it + 1 < 32) { load_stage(cur ^ 1, (it + 1) * 16); CP_COMMIT(); }
        const uint32_t* Ab = &As[cur * 1280];
        const uint32_t* Bb = &Bs[cur * 8320];
#pragma unroll
        for (int ks = 0; ks < 16; ks += 8) {
            uint32_t af[2][4];
#pragma unroll
            for (int mt = 0; mt < 2; mt++) {
                int rb = (wr * 32 + mt * 16 + g) * 20 + ks;
                af[mt][0] = Ab[rb + tig];       af[mt][1] = Ab[rb + 160 + tig];
                af[mt][2] = Ab[rb + tig + 4];   af[mt][3] = Ab[rb + 160 + tig + 4];
            }
#pragma unroll
            for (int nt = 0; nt < 8; nt++) {
                int cb = wc * 64 + nt * 8 + g;
                uint32_t b0 = Bb[(ks + tig) * 520 + cb];
                uint32_t b1 = Bb[(ks + tig + 4) * 520 + cb];
                mma_tf32(acc[0][nt], af[0], b0, b1);
                mma_tf32(acc[1][nt], af[1], b0, b1);
            }
        }
        __syncthreads();
    }

    float rsm[4] = {0, 0, 0, 0}, rsq[4] = {0, 0, 0, 0};
#pragma unroll
    for (int mt = 0; mt < 2; mt++)
#pragma unroll
        for (int nt = 0; nt < 8; nt++) {
            int c0 = wc * 64 + nt * 8 + 2 * tig;
            float v0 = acc[mt][nt][0] + sB[c0], v1 = acc[mt][nt][1] + sB[c0 + 1];
            float v2 = acc[mt][nt][2] + sB[c0], v3 = acc[mt][nt][3] + sB[c0 + 1];
            acc[mt][nt][0] = v0; acc[mt][nt][1] = v1; acc[mt][nt][2] = v2; acc[mt][nt][3] = v3;
            rsm[mt * 2 + 0] += v0 + v1; rsq[mt * 2 + 0] += v0 * v0 + v1 * v1;
            rsm[mt * 2 + 1] += v2 + v3; rsq[mt * 2 + 1] += v2 * v2 + v3 * v3;
        }
#pragma unroll
    for (int off = 1; off < 4; off <<= 1)
#pragma unroll
        for (int q = 0; q < 4; q++) {
            rsm[q] += __shfl_xor_sync(0xffffffffu, rsm[q], off);
            rsq[q] += __shfl_xor_sync(0xffffffffu, rsq[q], off);
        }
    if (tig == 0) {
#pragma unroll
        for (int q = 0; q < 4; q++) {
            int row = wr * 32 + (q >> 1) * 16 + (q & 1) * 8 + g;
            ps[row * 8 + wc] = rsm[q]; pq[row * 8 + wc] = rsq[q];
        }
    }
    __syncthreads();
    float mv[4], rv[4];
#pragma unroll
    for (int q = 0; q < 4; q++) {
        int row = wr * 32 + (q >> 1) * 16 + (q & 1) * 8 + g;
        float s = 0.f, s2 = 0.f;
#pragma unroll
        for (int j = 0; j < 8; j++) { s += ps[row * 8 + j]; s2 += pq[row * 8 + j]; }
        float m = s * (1.f / 512.f);
        float var = s2 * (1.f / 512.f) - m * m;
        mv[q] = m; rv[q] = rsqrtf(var + EPSV);
    }
#pragma unroll
    for (int mt = 0; mt < 2; mt++)
#pragma unroll
        for (int nt = 0; nt < 8; nt++) {
            int c0 = wc * 64 + nt * 8 + 2 * tig;
            int q0 = mt * 2;
            int row0 = t0 + wr * 32 + mt * 16 + g;
            float u0 = gelu_exact((acc[mt][nt][0] - mv[q0]) * rv[q0] * sG[c0] + sBt[c0]);
            float u1 = gelu_exact((acc[mt][nt][1] - mv[q0]) * rv[q0] * sG[c0 + 1] + sBt[c0 + 1]);
            *(float2*)&g_oact[(size_t)row0 * 512 + c0] = make_float2(f2tf_f(u0), f2tf_f(u1));
            float u2 = gelu_exact((acc[mt][nt][2] - mv[q0 + 1]) * rv[q0 + 1] * sG[c0] + sBt[c0]);
            float u3 = gelu_exact((acc[mt][nt][3] - mv[q0 + 1]) * rv[q0 + 1] * sG[c0 + 1] + sBt[c0 + 1]);
            *(float2*)&g_oact[(size_t)(row0 + 8) * 512 + c0] = make_float2(f2tf_f(u2), f2tf_f(u3));
        }
}

// ============================================================================
// K5: out = xn + oact @ oW2 + ob2.
// ============================================================================
#define K5_SMEM 78848
__global__ void __launch_bounds__(512) k_out2_mma(
    const float* __restrict__ ob2, float* __restrict__ out)
{
    extern __shared__ __align__(16) char dsm[];
    uint32_t* As = (uint32_t*)dsm;
    uint32_t* Bs = (uint32_t*)(dsm + 10240);
    float* sB = (float*)(dsm + 76800);

    const int t0 = blockIdx.x * 64;
    const int tid = threadIdx.x, w = tid >> 5, l = tid & 31;
    const int wr = w >> 3, wc = w & 7, g = l >> 2, tig = l & 3;

    sB[tid] = ob2[tid];

    float acc[2][8][4];
#pragma unroll
    for (int mt = 0; mt < 2; mt++)
#pragma unroll
        for (int nt = 0; nt < 8; nt++)
#pragma unroll
            for (int i = 0; i < 4; i++) acc[mt][nt][i] = 0.f;

    const int ar = tid >> 2, ac4 = (tid & 3) * 4;
    const float* Ap = g_oact + (size_t)(t0 + (ar & 63)) * 512 + ac4;

    auto load_stage = [&](int s, int k0) {
        if (tid < 256) cp16(&As[s * 1280 + ar * 20 + ac4], Ap + k0);
#pragma unroll
        for (int i = 0; i < 4; i++) {
            int idx = tid + 512 * i;
            int kk = idx >> 7, c4 = (idx & 127) * 4;
            cp16(&Bs[s * 8320 + kk * 520 + c4], g_oW2t + (size_t)(k0 + kk) * 512 + c4);
        }
    };

    load_stage(0, 0); CP_COMMIT();
    for (int it = 0; it < 32; it++) {
        const int cur = it & 1;
        CP_WAIT_ALL();
        __syncthreads();
        if (it + 1 < 32) { load_stage(cur ^ 1, (it + 1) * 16); CP_COMMIT(); }
        const uint32_t* Ab = &As[cur * 1280];
        const uint32_t* Bb = &Bs[cur * 8320];
#pragma unroll
        for (int ks = 0; ks < 16; ks += 8) {
            uint32_t af[2][4];
#pragma unroll
            for (int mt = 0; mt < 2; mt++) {
                int rb = (wr * 32 + mt * 16 + g) * 20 + ks;
                af[mt][0] = Ab[rb + tig];       af[mt][1] = Ab[rb + 160 + tig];
                af[mt][2] = Ab[rb + tig + 4];   af[mt][3] = Ab[rb + 160 + tig + 4];
            }
#pragma unroll
            for (int nt = 0; nt < 8; nt++) {
                int cb = wc * 64 + nt * 8 + g;
                uint32_t b0 = Bb[(ks + tig) * 520 + cb];
                uint32_t b1 = Bb[(ks + tig + 4) * 520 + cb];
                mma_tf32(acc[0][nt], af[0], b0, b1);
                mma_tf32(acc[1][nt], af[1], b0, b1);
            }
        }
        __syncthreads();
    }

#pragma unroll
    for (int mt = 0; mt < 2; mt++)
#pragma unroll
        for (int nt = 0; nt < 8; nt++) {
            int c0 = wc * 64 + nt * 8 + 2 * tig;
            int row0 = t0 + wr * 32 + mt * 16 + g;
            size_t o0 = (size_t)row0 * 512 + c0;
            size_t o1 = (size_t)(row0 + 8) * 512 + c0;
            float2 x0 = *(const float2*)&g_xn[o0];
            float2 x1 = *(const float2*)&g_xn[o1];
            *(float2*)&out[o0] = make_float2(acc[mt][nt][0] + sB[c0] + x0.x,
                                             acc[mt][nt][1] + sB[c0 + 1] + x0.y);
            *(float2*)&out[o1] = make_float2(acc[mt][nt][2] + sB[c0] + x1.x,
                                             acc[mt][nt][3] + sB[c0 + 1] + x1.y);
        }
}

// ============================================================================
extern "C" void kernel_launch(void* const* d_in, const int* in_sizes, int n_in,
                              void* d_out, int out_size)
{
    (void)in_sizes; (void)n_in; (void)out_size;
    const float* x    = (const float*)d_in[0];
    const float* ng   = (const float*)d_in[1];
    const float* nb   = (const float*)d_in[2];
    const float* hW1  = (const float*)d_in[3];
    const float* hb1  = (const float*)d_in[4];
    const float* hlg  = (const float*)d_in[5];
    const float* hlb  = (const float*)d_in[6];
    const float* hW2  = (const float*)d_in[7];
    const float* hb2  = (const float*)d_in[8];
    const float* attr = (const float*)d_in[9];
    const float* dynm = (const float*)d_in[10];
    const float* gW   = (const float*)d_in[11];
    const float* gb   = (const float*)d_in[12];
    const float* oW1  = (const float*)d_in[13];
    const float* ob1  = (const float*)d_in[14];
    const float* olg  = (const float*)d_in[15];
    const float* olb  = (const float*)d_in[16];
    const float* oW2  = (const float*)d_in[17];
    const float* ob2  = (const float*)d_in[18];
    float* out = (float*)d_out;

    cudaFuncSetAttribute(k_head1_mma, cudaFuncAttributeMaxDynamicSharedMemorySize, K2_SMEM);
    cudaFuncSetAttribute(k_head2_mma, cudaFuncAttributeMaxDynamicSharedMemorySize, K3_SMEM);
    cudaFuncSetAttribute(k_out1_mma,  cudaFuncAttributeMaxDynamicSharedMemorySize, K4_SMEM);
    cudaFuncSetAttribute(k_out2_mma,  cudaFuncAttributeMaxDynamicSharedMemorySize, K5_SMEM);

    k_prep<<<4864, 256>>>(hW1, hW2, dynm, oW1, oW2);
    k_ln_gate<<<8192, 128>>>(x, ng, nb, gW, gb);

    dim3 gh(T_TOK / 64, 4);
    k_head1_mma<<<gh, 256, K2_SMEM>>>(hb1, hlg, hlb);
    k_head2_mma<<<gh, 256, K3_SMEM>>>(hb2, attr);

    k_out1_mma<<<T_TOK / 64, 512, K4_SMEM>>>(ob1, olg, olb);
    k_out2_mma<<<T_TOK / 64, 512, K5_SMEM>>>(ob2, out);
}